// round 6
// baseline (speedup 1.0000x reference)
#include <cuda_runtime.h>
#include <cstddef>

// Scratch (allocation-free rule: __device__ globals)
__device__ float g_s1[32*31*64*64];
__device__ float g_s2[32*31*64*64];
__device__ float g_s3[32*31*64*64];
__device__ float g_hb[32*32*64*64];

// ---------------------------------------------------------------------------
// Spatial stage: out[b][o][f][w] = relu(bias[f][o] +
//     sum_{i<Cin,kh<64,kw<3} inp[b][i][kh][w+kw-1] * W[f][o][i][kh][kw])
// Grid: (f=64, bgroup=8), block 256 = 4 b-subblocks x 64 threads.
// Thread tile: 8 o (stride 4) x 4 w  => 32 accumulators.
// ---------------------------------------------------------------------------
extern "C" __global__ void __launch_bounds__(256,2) spatial_kernel(
    const float* __restrict__ inp, const float* __restrict__ Wt,
    const float* __restrict__ bias, float* __restrict__ outp, int Cin)
{
  extern __shared__ float sm[];
  float* s_in = sm;               // 4 * 64*66 floats (rows padded with zeros)
  float* s_w  = sm + 4*64*66;     // 32*193 floats (row 31 zeroed, pitch 193 kills conflicts)

  const int f = blockIdx.x;
  const int t = threadIdx.x;
  const int bsub = t >> 6, tl = t & 63;
  const int b = blockIdx.y*4 + bsub;
  const int ws = tl >> 2, os = tl & 3;
  const int w0 = ws*4;
  float* my_in = s_in + bsub*(64*66);

  // zero left/right pads once (persist across i iterations), zero weight row o=31
  my_in[tl*66]      = 0.f;
  my_in[tl*66 + 65] = 0.f;
  for (int r = t; r < 193; r += 256) s_w[31*193 + r] = 0.f;

  float acc[8][4];
  #pragma unroll
  for (int j=0;j<8;j++)
    #pragma unroll
    for (int p=0;p<4;p++) acc[j][p]=0.f;

  #pragma unroll 1
  for (int i=0;i<Cin;i++){
    __syncthreads();
    const float* gin = inp + ((size_t)(b*Cin + i) << 12);
    for (int idx = tl; idx < 4096; idx += 64)
      my_in[(idx>>6)*66 + 1 + (idx&63)] = gin[idx];
    for (int idx = t; idx < 31*192; idx += 256){
      int o = idx/192, r = idx - o*192;
      s_w[o*193 + r] = Wt[((size_t)(f*31 + o)*Cin + i)*192 + r];
    }
    __syncthreads();

    for (int kh=0; kh<64; kh++){
      const float* ir = my_in + kh*66 + w0;   // logical w0-1 .. w0+4 (pad offset +1)
      float i0=ir[0],i1=ir[1],i2=ir[2],i3=ir[3],i4=ir[4],i5=ir[5];
      #pragma unroll
      for (int j=0;j<8;j++){
        const float* wr = s_w + (os + 4*j)*193 + kh*3;
        float wA=wr[0], wB=wr[1], wC=wr[2];
        acc[j][0] += wA*i0 + wB*i1 + wC*i2;
        acc[j][1] += wA*i1 + wB*i2 + wC*i3;
        acc[j][2] += wA*i2 + wB*i3 + wC*i4;
        acc[j][3] += wA*i3 + wB*i4 + wC*i5;
      }
    }
  }

  #pragma unroll
  for (int j=0;j<8;j++){
    int o = os + 4*j;
    if (o < 31){
      float bv = bias[f*31 + o];
      float* op = outp + (((size_t)(b*31 + o))*64 + f)*64 + w0;
      #pragma unroll
      for (int p=0;p<4;p++) op[p] = fmaxf(acc[j][p] + bv, 0.f);
    }
  }
}

// ---------------------------------------------------------------------------
// Spectral fused conv-a (9x9, Cin->64, relu) + conv-b (1x1, 64->32, relu).
// Grid: (16 tiles of 16x16, b=32). Block 256.
// conv-a: thread = (pixel-group pg<32, ch-slot cs<8): 8 px (one row segment)
//         x 8 ch = 64 acc; input row cached in 16 regs, slid across dx.
// ha staged in smem (reusing the wa buffer), then conv-b: thread = (pq<64,c4<4):
//         4 px x 8 out-ch.
// ---------------------------------------------------------------------------
extern "C" __global__ void __launch_bounds__(256,2) spec_ab_kernel(
    const float* __restrict__ s3, const float* __restrict__ wa,
    const float* __restrict__ ba, const float* __restrict__ wb,
    const float* __restrict__ bb, float* __restrict__ hb,
    int c0, int Cin)
{
  extern __shared__ float sm[];
  float* in_sh = sm;                   // 3*24*24 = 1728
  float* big   = sm + 1728;            // max(64*Ck=15552, 256*65=16640)
  float* wb_sh = sm + 1728 + 16640;    // 32*65

  const int b = blockIdx.y;
  const int tile = blockIdx.x;
  const int ty0 = (tile>>2)*16, tx0 = (tile&3)*16;
  const int t = threadIdx.x;
  const int Ck = Cin*81;

  for (int idx = t; idx < Cin*576; idx += 256){
    int ci = idx/576, r = idx - ci*576;
    int yy = r/24, xx = r - yy*24;
    int gy = ty0-4+yy, gx = tx0-4+xx;
    float v = 0.f;
    if ((unsigned)gy < 64u && (unsigned)gx < 64u)
      v = s3[(((size_t)(b*31 + c0 + ci))*64 + gy)*64 + gx];
    in_sh[idx] = v;
  }
  for (int idx = t; idx < 64*Ck; idx += 256) big[idx] = wa[idx];
  for (int idx = t; idx < 2048; idx += 256){
    int c = idx>>6, k = idx&63;
    wb_sh[c*65 + k] = wb[idx];
  }
  __syncthreads();

  const int pg = t>>3, cs = t&7;
  const int y = pg>>1, xb = (pg&1)*8;

  float acc[8][8];
  #pragma unroll
  for (int j=0;j<8;j++){
    float bv = ba[cs*8+j];
    #pragma unroll
    for (int p=0;p<8;p++) acc[j][p] = bv;
  }

  #pragma unroll 1
  for (int ci=0;ci<Cin;ci++){
    #pragma unroll 1
    for (int dy=0;dy<9;dy++){
      const float* row = in_sh + (ci*24 + y + dy)*24 + xb;
      float r[16];
      #pragma unroll
      for (int q=0;q<4;q++){
        float4 v4 = *(const float4*)(row + q*4);
        r[4*q]=v4.x; r[4*q+1]=v4.y; r[4*q+2]=v4.z; r[4*q+3]=v4.w;
      }
      #pragma unroll
      for (int dx=0;dx<9;dx++){
        const int k = (ci*9+dy)*9 + dx;
        #pragma unroll
        for (int j=0;j<8;j++){
          float w = big[(cs*8+j)*Ck + k];
          #pragma unroll
          for (int p=0;p<8;p++) acc[j][p] += w * r[p+dx];
        }
      }
    }
  }
  __syncthreads();   // done reading wa; reuse buffer for ha
  #pragma unroll
  for (int j=0;j<8;j++){
    int ch = cs*8+j;
    #pragma unroll
    for (int p=0;p<8;p++)
      big[(pg*8+p)*65 + ch] = fmaxf(acc[j][p], 0.f);
  }
  __syncthreads();

  const int pq = t>>2, c4 = t&3;
  float a2[4][8];
  #pragma unroll
  for (int j=0;j<8;j++){
    float bv = bb[c4*8+j];
    #pragma unroll
    for (int p=0;p<4;p++) a2[p][j]=bv;
  }
  #pragma unroll 4
  for (int k=0;k<64;k++){
    float v[4];
    #pragma unroll
    for (int p=0;p<4;p++) v[p] = big[(pq*4+p)*65 + k];
    #pragma unroll
    for (int j=0;j<8;j++){
      float w = wb_sh[(c4*8+j)*65 + k];
      #pragma unroll
      for (int p=0;p<4;p++) a2[p][j] += w*v[p];
    }
  }
  #pragma unroll
  for (int p=0;p<4;p++){
    int px = pq*4+p, yy = px>>4, xx = px&15;
    int gy = ty0+yy, gx = tx0+xx;
    #pragma unroll
    for (int j=0;j<8;j++){
      int c = c4*8+j;
      hb[(((size_t)(b*32 + c))*64 + gy)*64 + gx] = fmaxf(a2[p][j], 0.f);
    }
  }
}

// ---------------------------------------------------------------------------
// Spectral conv-c (5x5, 32->1) + residual add + NHWC transpose store.
// Grid: (8 tiles of 32x16, b=32). Block 256, 2 px/thread.
// ---------------------------------------------------------------------------
extern "C" __global__ void __launch_bounds__(256,2) spec_c_kernel(
    const float* __restrict__ hb, const float* __restrict__ wc,
    const float* __restrict__ bc, const float* __restrict__ s3,
    float* __restrict__ outp, int cbr)
{
  extern __shared__ float sm[];
  float* in_sh = sm;          // 32*20*36 = 23040
  float* wc_sh = sm + 23040;  // 800

  const int b = blockIdx.y;
  const int tile = blockIdx.x;
  const int ty0 = (tile>>1)*16, tx0 = (tile&1)*32;
  const int t = threadIdx.x;

  for (int idx=t; idx<800; idx+=256) wc_sh[idx] = wc[idx];
  for (int idx=t; idx<23040; idx+=256){
    int c = idx/720, r = idx - c*720;
    int yy = r/36, xx = r - yy*36;
    int gy = ty0-2+yy, gx = tx0-2+xx;
    float v=0.f;
    if ((unsigned)gy<64u && (unsigned)gx<64u)
      v = hb[(((size_t)(b*32+c))*64+gy)*64+gx];
    in_sh[idx]=v;
  }
  __syncthreads();

  const int px0 = t*2;
  const int y = px0>>5, x = px0&31;
  float a0 = bc[0], a1 = a0;
  #pragma unroll 1
  for (int c=0;c<32;c++){
    #pragma unroll
    for (int dy=0;dy<5;dy++){
      const float* row = in_sh + (c*20 + y + dy)*36 + x;
      float r0=row[0],r1=row[1],r2=row[2],r3=row[3],r4=row[4],r5=row[5];
      const float* wr = wc_sh + c*25 + dy*5;
      a0 += wr[0]*r0 + wr[1]*r1 + wr[2]*r2 + wr[3]*r3 + wr[4]*r4;
      a1 += wr[0]*r1 + wr[1]*r2 + wr[2]*r3 + wr[3]*r4 + wr[4]*r5;
    }
  }
  const int gy = ty0+y, gx = tx0+x;
  const float* s3p = s3 + (((size_t)(b*31+cbr))*64 + gy)*64 + gx;
  float* op = outp + (((size_t)(b*64+gy))*64 + gx)*31 + cbr;
  op[0]  = s3p[0] + a0;
  op[31] = s3p[1] + a1;
}

// ---------------------------------------------------------------------------
extern "C" void kernel_launch(void* const* d_in, const int* in_sizes, int n_in,
                              void* d_out, int out_size)
{
  (void)in_sizes; (void)n_in; (void)out_size;
  const float* x    = (const float*)d_in[0];
  const float* W1   = (const float*)d_in[1];
  const float* b1   = (const float*)d_in[2];
  const float* W2   = (const float*)d_in[3];
  const float* b2   = (const float*)d_in[4];
  const float* W3   = (const float*)d_in[5];
  const float* b3   = (const float*)d_in[6];
  const float* We1a = (const float*)d_in[7];
  const float* be1a = (const float*)d_in[8];
  const float* We1b = (const float*)d_in[9];
  const float* be1b = (const float*)d_in[10];
  const float* We1c = (const float*)d_in[11];
  const float* be1c = (const float*)d_in[12];
  const float* We2a = (const float*)d_in[13];
  const float* be2a = (const float*)d_in[14];
  const float* We2b = (const float*)d_in[15];
  const float* be2b = (const float*)d_in[16];
  const float* We2c = (const float*)d_in[17];
  const float* be2c = (const float*)d_in[18];

  float *s1,*s2,*s3,*hbuf;
  cudaGetSymbolAddress((void**)&s1, g_s1);
  cudaGetSymbolAddress((void**)&s2, g_s2);
  cudaGetSymbolAddress((void**)&s3, g_s3);
  cudaGetSymbolAddress((void**)&hbuf, g_hb);

  const int SPAT_SM = (4*64*66 + 32*193)*4;      // 92288 B
  const int AB_SM   = (1728 + 16640 + 2080)*4;   // 81792 B
  const int C_SM    = (23040 + 800)*4;           // 95360 B
  cudaFuncSetAttribute(spatial_kernel, cudaFuncAttributeMaxDynamicSharedMemorySize, SPAT_SM);
  cudaFuncSetAttribute(spec_ab_kernel, cudaFuncAttributeMaxDynamicSharedMemorySize, AB_SM);
  cudaFuncSetAttribute(spec_c_kernel,  cudaFuncAttributeMaxDynamicSharedMemorySize, C_SM);

  spatial_kernel<<<dim3(64,8),256,SPAT_SM>>>(x,  W1, b1, s1, 1);
  spatial_kernel<<<dim3(64,8),256,SPAT_SM>>>(s1, W2, b2, s2, 31);
  spatial_kernel<<<dim3(64,8),256,SPAT_SM>>>(s2, W3, b3, s3, 31);

  float* out = (float*)d_out;
  for (int br=0; br<31; br++){
    const float *wa,*ba,*wb,*bb,*wc,*bc; int c0, Cin;
    if (br==0){
      Cin=2; c0=0;
      wa=We1a;           ba=be1a;      wb=We1b;        bb=be1b;      wc=We1c;      bc=be1c;
    } else if (br==30){
      Cin=2; c0=29;
      wa=We1a+64*2*81;   ba=be1a+64;   wb=We1b+32*64;  bb=be1b+32;   wc=We1c+800;  bc=be1c+1;
    } else {
      int m=br-1; Cin=3; c0=m;
      wa=We2a+(size_t)m*64*3*81; ba=be2a+(size_t)m*64;
      wb=We2b+(size_t)m*32*64;   bb=be2b+(size_t)m*32;
      wc=We2c+(size_t)m*800;     bc=be2c+m;
    }
    spec_ab_kernel<<<dim3(16,32),256,AB_SM>>>(s3, wa, ba, wb, bb, hbuf, c0, Cin);
    spec_c_kernel<<<dim3(8,32),256,C_SM>>>(hbuf, wc, bc, s3, out, br);
  }
}

// round 7
// speedup vs baseline: 1.2231x; 1.2231x over previous
#include <cuda_runtime.h>
#include <cstddef>

typedef unsigned long long ull;

// Scratch (allocation-free rule: __device__ globals)
__device__ float g_s1[32*31*64*64];
__device__ float g_s2[32*31*64*64];
__device__ float g_s3[32*31*64*64];
__device__ float g_hb[31u*32*32*64*64];   // per-branch hb, 520MB

// ---- packed f32x2 helpers -------------------------------------------------
__device__ __forceinline__ void fma2(ull& d, ull a, ull b){
  asm("fma.rn.f32x2 %0, %1, %2, %0;" : "+l"(d) : "l"(a), "l"(b));
}
__device__ __forceinline__ ull dup2(float v){
  ull r; asm("mov.b64 %0, {%1, %1};" : "=l"(r) : "f"(v)); return r;
}
__device__ __forceinline__ ull pack2(float lo, float hi){
  ull r; asm("mov.b64 %0, {%1, %2};" : "=l"(r) : "f"(lo), "f"(hi)); return r;
}
__device__ __forceinline__ float2 ull2f(ull v){
  float2 f; asm("mov.b64 {%0, %1}, %2;" : "=f"(f.x), "=f"(f.y) : "l"(v)); return f;
}

// ---------------------------------------------------------------------------
// Spatial stage: out[b][o][f][w] = relu(bias[f][o] +
//     sum_{i<Cin,kh<64,kw<3} inp[b][i][kh][w+kw-1] * W[f][o][i][kh][kw])
// Grid: (f=64, bgroup=8), block 256 = 4 b-subblocks x 64 threads.
// Thread tile: 4 o-PAIRS (o = os*8 + 2j2 + {0,1}) x 4 w => 16 f32x2 accs.
// Weights transposed in smem: swT[(kh*3+ki)*34 + o] -> LDS.64 gives o-pair.
// ---------------------------------------------------------------------------
extern "C" __global__ void __launch_bounds__(256,2) spatial_kernel(
    const float* __restrict__ inp, const float* __restrict__ Wt,
    const float* __restrict__ bias, float* __restrict__ outp, int Cin)
{
  extern __shared__ float sm[];
  float* s_in = sm;               // 4 * 64*66 floats (rows padded with zeros)
  float* swT  = sm + 4*64*66;     // 192*34 floats, [r][o] transposed, col 31 zero

  const int f = blockIdx.x;
  const int t = threadIdx.x;
  const int bsub = t >> 6, tl = t & 63;
  const int b = blockIdx.y*4 + bsub;
  const int ws = tl >> 2, os = tl & 3;
  const int w0 = ws*4;
  float* my_in = s_in + bsub*(64*66);

  // persistent pads / zero weight column o=31
  my_in[tl*66]      = 0.f;
  my_in[tl*66 + 65] = 0.f;
  if (t < 192) swT[t*34 + 31] = 0.f;

  ull acc[4][4];
  #pragma unroll
  for (int j2=0;j2<4;j2++)
    #pragma unroll
    for (int p=0;p<4;p++) acc[j2][p] = 0ull;

  #pragma unroll 1
  for (int i=0;i<Cin;i++){
    __syncthreads();
    const float* gin = inp + ((size_t)(b*Cin + i) << 12);
    for (int idx = tl; idx < 4096; idx += 64)
      my_in[(idx>>6)*66 + 1 + (idx&63)] = gin[idx];
    for (int idx = t; idx < 31*192; idx += 256){
      int o = idx/192, r = idx - o*192;
      swT[r*34 + o] = Wt[((size_t)(f*31 + o)*Cin + i)*192 + r];
    }
    __syncthreads();

    #pragma unroll 1
    for (int kh=0; kh<64; kh++){
      const float* ir = my_in + kh*66 + w0;   // logical w0-1 .. w0+4
      float2 u0 = *(const float2*)(ir);
      float2 u1 = *(const float2*)(ir+2);
      float2 u2 = *(const float2*)(ir+4);
      ull rr[6];
      rr[0]=dup2(u0.x); rr[1]=dup2(u0.y); rr[2]=dup2(u1.x);
      rr[3]=dup2(u1.y); rr[4]=dup2(u2.x); rr[5]=dup2(u2.y);
      const float* wbp = swT + kh*(3*34) + os*8;
      ull wp[3][4];
      #pragma unroll
      for (int ki=0;ki<3;ki++)
        #pragma unroll
        for (int j2=0;j2<4;j2++)
          wp[ki][j2] = *(const ull*)(wbp + ki*34 + 2*j2);
      #pragma unroll
      for (int ki=0;ki<3;ki++)
        #pragma unroll
        for (int j2=0;j2<4;j2++)
          #pragma unroll
          for (int p=0;p<4;p++)
            fma2(acc[j2][p], wp[ki][j2], rr[p+ki]);
    }
  }

  #pragma unroll
  for (int j2=0;j2<4;j2++){
    int o0 = os*8 + 2*j2;
    float b0 = bias[f*31 + o0];
    float b1 = (o0+1 < 31) ? bias[f*31 + o0 + 1] : 0.f;
    float* op0 = outp + (((size_t)(b*31 + o0))*64 + f)*64 + w0;
    float* op1 = outp + (((size_t)(b*31 + o0+1))*64 + f)*64 + w0;
    #pragma unroll
    for (int p=0;p<4;p++){
      float2 v = ull2f(acc[j2][p]);
      op0[p] = fmaxf(v.x + b0, 0.f);
      if (o0+1 < 31) op1[p] = fmaxf(v.y + b1, 0.f);
    }
  }
}

// ---------------------------------------------------------------------------
// Spectral fused conv-a (9x9, Cin->64, relu) + conv-b (1x1, 64->32, relu).
// Batched over all 31 branches via blockIdx.z.
// Grid: (16 tiles of 16x16, b=32, br=31). Block 256.
// conv-a: thread = (pg<32, cs<8): 8 px x 4 ch-PAIRS = 32 f32x2 accs.
//   Weights transposed in smem bigW[k*66+ch] -> LDS.64 ch-pairs; pixels dup2'd.
// ha restaged channel-major big2[ch*258+px]; conv-b: thread = (pq<64,c4<4):
//   2 px-pairs (LDS.64) x 8 out-ch, wb duplicated in smem (LDS.64 dup).
// ---------------------------------------------------------------------------
extern "C" __global__ void __launch_bounds__(256,2) spec_ab_kernel(
    const float* __restrict__ s3,
    const float* __restrict__ We1a, const float* __restrict__ be1a,
    const float* __restrict__ We1b, const float* __restrict__ be1b,
    const float* __restrict__ We2a, const float* __restrict__ be2a,
    const float* __restrict__ We2b, const float* __restrict__ be2b,
    float* __restrict__ hb_all)
{
  extern __shared__ float sm[];
  float* in_sh = sm;                   // 3*24*24 = 1728
  float* bigW  = sm + 1728;            // 16640: conv-a weights [k*66+ch], then ha [ch*258+px]
  float* wbdup = sm + 1728 + 16640;    // 32*130 duplicated wb

  const int br = blockIdx.z;
  const float *wa, *ba, *wb, *bb; int c0, Cin;
  if (br == 0){
    Cin=2; c0=0;  wa=We1a;        ba=be1a;    wb=We1b;      bb=be1b;
  } else if (br == 30){
    Cin=2; c0=29; wa=We1a+10368;  ba=be1a+64; wb=We1b+2048; bb=be1b+32;
  } else {
    int m = br-1; Cin=3; c0=m;
    wa=We2a+(size_t)m*15552; ba=be2a+(size_t)m*64;
    wb=We2b+(size_t)m*2048;  bb=be2b+(size_t)m*32;
  }
  const int Ck = Cin*81;

  const int b = blockIdx.y;
  const int tile = blockIdx.x;
  const int ty0 = (tile>>2)*16, tx0 = (tile&3)*16;
  const int t = threadIdx.x;

  for (int idx = t; idx < Cin*576; idx += 256){
    int ci = idx/576, r = idx - ci*576;
    int yy = r/24, xx = r - yy*24;
    int gy = ty0-4+yy, gx = tx0-4+xx;
    float v = 0.f;
    if ((unsigned)gy < 64u && (unsigned)gx < 64u)
      v = s3[(((size_t)(b*31 + c0 + ci))*64 + gy)*64 + gx];
    in_sh[idx] = v;
  }
  for (int idx = t; idx < 64*Ck; idx += 256){
    int ch = idx/Ck, k = idx - ch*Ck;
    bigW[k*66 + ch] = wa[idx];
  }
  for (int idx = t; idx < 2048; idx += 256){
    int c = idx>>6, k = idx&63;
    float w = wb[idx];
    wbdup[c*130 + 2*k]   = w;
    wbdup[c*130 + 2*k+1] = w;
  }
  __syncthreads();

  const int pg = t>>3, cs = t&7;
  const int y = pg>>1, xb = (pg&1)*8;

  ull acc[4][8];
  #pragma unroll
  for (int j2=0;j2<4;j2++){
    float2 bv = *(const float2*)(ba + cs*8 + 2*j2);
    ull bp = pack2(bv.x, bv.y);
    #pragma unroll
    for (int p=0;p<8;p++) acc[j2][p] = bp;
  }

  #pragma unroll 1
  for (int ci=0;ci<Cin;ci++){
    #pragma unroll 1
    for (int dy=0;dy<9;dy++){
      const float* row = in_sh + (ci*24 + y + dy)*24 + xb;
      ull rr[16];
      #pragma unroll
      for (int q=0;q<4;q++){
        float4 v4 = *(const float4*)(row + q*4);
        rr[4*q]   = dup2(v4.x); rr[4*q+1] = dup2(v4.y);
        rr[4*q+2] = dup2(v4.z); rr[4*q+3] = dup2(v4.w);
      }
      const int kbase = (ci*9+dy)*9;
      #pragma unroll
      for (int dx=0;dx<9;dx++){
        const float* wr = bigW + (kbase+dx)*66 + cs*8;
        ull w0_ = *(const ull*)(wr);
        ull w1_ = *(const ull*)(wr+2);
        ull w2_ = *(const ull*)(wr+4);
        ull w3_ = *(const ull*)(wr+6);
        #pragma unroll
        for (int p=0;p<8;p++){
          fma2(acc[0][p], w0_, rr[p+dx]);
          fma2(acc[1][p], w1_, rr[p+dx]);
          fma2(acc[2][p], w2_, rr[p+dx]);
          fma2(acc[3][p], w3_, rr[p+dx]);
        }
      }
    }
  }
  __syncthreads();   // done reading bigW; reuse buffer channel-major for ha
  float* big2 = bigW;
  #pragma unroll
  for (int j2=0;j2<4;j2++){
    int ch = cs*8 + 2*j2;
    #pragma unroll
    for (int p=0;p<8;p++){
      float2 v = ull2f(acc[j2][p]);
      int px = pg*8 + p;
      big2[ch*258 + px]     = fmaxf(v.x, 0.f);
      big2[(ch+1)*258 + px] = fmaxf(v.y, 0.f);
    }
  }
  __syncthreads();

  const int pq = t>>2, c4 = t&3;
  ull a2[8][2];
  #pragma unroll
  for (int j=0;j<8;j++){
    ull d = dup2(bb[c4*8+j]);
    a2[j][0]=d; a2[j][1]=d;
  }
  #pragma unroll 4
  for (int k=0;k<64;k++){
    const float* hrow = big2 + k*258 + pq*4;
    ull v0 = *(const ull*)(hrow);
    ull v1 = *(const ull*)(hrow+2);
    const float* wr = wbdup + (c4*8)*130 + 2*k;
    #pragma unroll
    for (int j=0;j<8;j++){
      ull wd = *(const ull*)(wr + j*130);
      fma2(a2[j][0], wd, v0);
      fma2(a2[j][1], wd, v1);
    }
  }

  float* hb = hb_all + (size_t)br * (32u*32*64*64);
  #pragma unroll
  for (int j=0;j<8;j++){
    int c = c4*8+j;
    #pragma unroll
    for (int q=0;q<2;q++){
      float2 v = ull2f(a2[j][q]);
      int px = pq*4 + 2*q;
      int yy = px>>4, xx = px&15;
      float2 st = make_float2(fmaxf(v.x,0.f), fmaxf(v.y,0.f));
      *(float2*)&hb[(((size_t)(b*32 + c))*64 + ty0+yy)*64 + tx0+xx] = st;
    }
  }
}

// ---------------------------------------------------------------------------
// Spectral conv-c (5x5, 32->1) + residual add + NHWC transpose store.
// Batched over branches via blockIdx.z. Grid: (8 tiles of 32x16, b=32, br=31).
// Block 256, 2 px/thread as one f32x2 accumulator; wc duplicated in smem.
// ---------------------------------------------------------------------------
extern "C" __global__ void __launch_bounds__(256,2) spec_c_kernel(
    const float* __restrict__ hb_all,
    const float* __restrict__ We1c, const float* __restrict__ be1c,
    const float* __restrict__ We2c, const float* __restrict__ be2c,
    const float* __restrict__ s3, float* __restrict__ outp)
{
  extern __shared__ float sm[];
  float* in_sh = sm;          // 32*20*36 = 23040
  float* wd    = sm + 23040;  // 800*2 duplicated wc

  const int br = blockIdx.z;
  const float *wc, *bc;
  if (br == 0)      { wc=We1c;                 bc=be1c;   }
  else if (br == 30){ wc=We1c+800;             bc=be1c+1; }
  else              { wc=We2c+(size_t)(br-1)*800; bc=be2c+(br-1); }
  const int cbr = br;
  const float* hb = hb_all + (size_t)br * (32u*32*64*64);

  const int b = blockIdx.y;
  const int tile = blockIdx.x;
  const int ty0 = (tile>>1)*16, tx0 = (tile&1)*32;
  const int t = threadIdx.x;

  for (int idx=t; idx<800; idx+=256){
    float w = wc[idx];
    wd[2*idx] = w; wd[2*idx+1] = w;
  }
  for (int idx=t; idx<23040; idx+=256){
    int c = idx/720, r = idx - c*720;
    int yy = r/36, xx = r - yy*36;
    int gy = ty0-2+yy, gx = tx0-2+xx;
    float v=0.f;
    if ((unsigned)gy<64u && (unsigned)gx<64u)
      v = hb[(((size_t)(b*32+c))*64+gy)*64+gx];
    in_sh[idx]=v;
  }
  __syncthreads();

  const int px0 = t*2;
  const int y = px0>>5, x = px0&31;
  ull acc = dup2(bc[0]);
  #pragma unroll 1
  for (int c=0;c<32;c++){
    #pragma unroll
    for (int dy=0;dy<5;dy++){
      const float* row = in_sh + (c*20 + y + dy)*36 + x;
      ull q0 = *(const ull*)(row);
      ull q2 = *(const ull*)(row+2);
      ull q4 = *(const ull*)(row+4);
      float2 f0 = ull2f(q0), f2v = ull2f(q2), f4 = ull2f(q4);
      ull q1 = pack2(f0.y, f2v.x);
      ull q3 = pack2(f2v.y, f4.x);
      const ull* wr = (const ull*)(wd + (c*25 + dy*5)*2);
      fma2(acc, wr[0], q0);
      fma2(acc, wr[1], q1);
      fma2(acc, wr[2], q2);
      fma2(acc, wr[3], q3);
      fma2(acc, wr[4], q4);
    }
  }
  float2 a = ull2f(acc);
  const int gy = ty0+y, gx = tx0+x;
  const float* s3p = s3 + (((size_t)(b*31+cbr))*64 + gy)*64 + gx;
  float* op = outp + (((size_t)(b*64+gy))*64 + gx)*31 + cbr;
  op[0]  = s3p[0] + a.x;
  op[31] = s3p[1] + a.y;
}

// ---------------------------------------------------------------------------
extern "C" void kernel_launch(void* const* d_in, const int* in_sizes, int n_in,
                              void* d_out, int out_size)
{
  (void)in_sizes; (void)n_in; (void)out_size;
  const float* x    = (const float*)d_in[0];
  const float* W1   = (const float*)d_in[1];
  const float* b1   = (const float*)d_in[2];
  const float* W2   = (const float*)d_in[3];
  const float* b2   = (const float*)d_in[4];
  const float* W3   = (const float*)d_in[5];
  const float* b3   = (const float*)d_in[6];
  const float* We1a = (const float*)d_in[7];
  const float* be1a = (const float*)d_in[8];
  const float* We1b = (const float*)d_in[9];
  const float* be1b = (const float*)d_in[10];
  const float* We1c = (const float*)d_in[11];
  const float* be1c = (const float*)d_in[12];
  const float* We2a = (const float*)d_in[13];
  const float* be2a = (const float*)d_in[14];
  const float* We2b = (const float*)d_in[15];
  const float* be2b = (const float*)d_in[16];
  const float* We2c = (const float*)d_in[17];
  const float* be2c = (const float*)d_in[18];

  float *s1,*s2,*s3,*hbuf;
  cudaGetSymbolAddress((void**)&s1, g_s1);
  cudaGetSymbolAddress((void**)&s2, g_s2);
  cudaGetSymbolAddress((void**)&s3, g_s3);
  cudaGetSymbolAddress((void**)&hbuf, g_hb);

  const int SPAT_SM = (4*64*66 + 192*34)*4;        // 93696 B
  const int AB_SM   = (1728 + 16640 + 32*130)*4;   // 90112 B
  const int C_SM    = (23040 + 1600)*4;            // 98560 B
  cudaFuncSetAttribute(spatial_kernel, cudaFuncAttributeMaxDynamicSharedMemorySize, SPAT_SM);
  cudaFuncSetAttribute(spec_ab_kernel, cudaFuncAttributeMaxDynamicSharedMemorySize, AB_SM);
  cudaFuncSetAttribute(spec_c_kernel,  cudaFuncAttributeMaxDynamicSharedMemorySize, C_SM);

  spatial_kernel<<<dim3(64,8),256,SPAT_SM>>>(x,  W1, b1, s1, 1);
  spatial_kernel<<<dim3(64,8),256,SPAT_SM>>>(s1, W2, b2, s2, 31);
  spatial_kernel<<<dim3(64,8),256,SPAT_SM>>>(s2, W3, b3, s3, 31);

  float* out = (float*)d_out;
  spec_ab_kernel<<<dim3(16,32,31),256,AB_SM>>>(s3, We1a,be1a,We1b,be1b,
                                               We2a,be2a,We2b,be2b, hbuf);
  spec_c_kernel<<<dim3(8,32,31),256,C_SM>>>(hbuf, We1c,be1c,We2c,be2c, s3, out);
}

// round 10
// speedup vs baseline: 1.2242x; 1.0009x over previous
#include <cuda_runtime.h>
#include <cstddef>

typedef unsigned long long ull;

// Scratch (allocation-free rule: __device__ globals)
__device__ float g_s1[32*31*64*64];
__device__ float g_s2[32*31*64*64];
__device__ float g_s3[32*31*64*64];
__device__ float g_hb[31u*32*32*64*64];   // per-branch hb, 520MB

// ---- packed f32x2 helpers -------------------------------------------------
__device__ __forceinline__ void fma2(ull& d, ull a, ull b){
  asm("fma.rn.f32x2 %0, %1, %2, %0;" : "+l"(d) : "l"(a), "l"(b));
}
__device__ __forceinline__ ull dup2(float v){
  ull r; asm("mov.b64 %0, {%1, %1};" : "=l"(r) : "f"(v)); return r;
}
__device__ __forceinline__ ull pack2(float lo, float hi){
  ull r; asm("mov.b64 %0, {%1, %2};" : "=l"(r) : "f"(lo), "f"(hi)); return r;
}
__device__ __forceinline__ float2 ull2f(ull v){
  float2 f; asm("mov.b64 {%0, %1}, %2;" : "=f"(f.x), "=f"(f.y) : "l"(v)); return f;
}

// ---------------------------------------------------------------------------
// Spatial stage: out[b][o][f][w] = relu(bias[f][o] +
//     sum_{i<Cin,kh<64,kw<3} inp[b][i][kh][w+kw-1] * W[f][o][i][kh][kw])
// Grid: (f=64, bgroup=8), block 256 = 4 b-subblocks x 64 threads.
// Thread tile: 4 o-PAIRS (o = os*8 + 2j2 + {0,1}) x 4 w => 16 f32x2 accs.
// Weights transposed in smem: swT[(kh*3+ki)*34 + o] -> LDS.64 gives o-pair.
// ---------------------------------------------------------------------------
extern "C" __global__ void __launch_bounds__(256,2) spatial_kernel(
    const float* __restrict__ inp, const float* __restrict__ Wt,
    const float* __restrict__ bias, float* __restrict__ outp, int Cin)
{
  extern __shared__ float sm[];
  float* s_in = sm;               // 4 * 64*66 floats (rows padded with zeros)
  float* swT  = sm + 4*64*66;     // 192*34 floats, [r][o] transposed, col 31 zero

  const int f = blockIdx.x;
  const int t = threadIdx.x;
  const int bsub = t >> 6, tl = t & 63;
  const int b = blockIdx.y*4 + bsub;
  const int ws = tl >> 2, os = tl & 3;
  const int w0 = ws*4;
  float* my_in = s_in + bsub*(64*66);

  // persistent pads / zero weight column o=31
  my_in[tl*66]      = 0.f;
  my_in[tl*66 + 65] = 0.f;
  if (t < 192) swT[t*34 + 31] = 0.f;

  ull acc[4][4];
  #pragma unroll
  for (int j2=0;j2<4;j2++)
    #pragma unroll
    for (int p=0;p<4;p++) acc[j2][p] = 0ull;

  #pragma unroll 1
  for (int i=0;i<Cin;i++){
    __syncthreads();
    const float* gin = inp + ((size_t)(b*Cin + i) << 12);
    for (int idx = tl; idx < 4096; idx += 64)
      my_in[(idx>>6)*66 + 1 + (idx&63)] = gin[idx];
    for (int idx = t; idx < 31*192; idx += 256){
      int o = idx/192, r = idx - o*192;
      swT[r*34 + o] = Wt[((size_t)(f*31 + o)*Cin + i)*192 + r];
    }
    __syncthreads();

    #pragma unroll 1
    for (int kh=0; kh<64; kh++){
      const float* ir = my_in + kh*66 + w0;   // logical w0-1 .. w0+4
      float2 u0 = *(const float2*)(ir);
      float2 u1 = *(const float2*)(ir+2);
      float2 u2 = *(const float2*)(ir+4);
      ull rr[6];
      rr[0]=dup2(u0.x); rr[1]=dup2(u0.y); rr[2]=dup2(u1.x);
      rr[3]=dup2(u1.y); rr[4]=dup2(u2.x); rr[5]=dup2(u2.y);
      const float* wbp = swT + kh*(3*34) + os*8;
      ull wp[3][4];
      #pragma unroll
      for (int ki=0;ki<3;ki++)
        #pragma unroll
        for (int j2=0;j2<4;j2++)
          wp[ki][j2] = *(const ull*)(wbp + ki*34 + 2*j2);
      #pragma unroll
      for (int ki=0;ki<3;ki++)
        #pragma unroll
        for (int j2=0;j2<4;j2++)
          #pragma unroll
          for (int p=0;p<4;p++)
            fma2(acc[j2][p], wp[ki][j2], rr[p+ki]);
    }
  }

  #pragma unroll
  for (int j2=0;j2<4;j2++){
    int o0 = os*8 + 2*j2;
    float b0 = bias[f*31 + o0];
    float b1 = (o0+1 < 31) ? bias[f*31 + o0 + 1] : 0.f;
    float* op0 = outp + (((size_t)(b*31 + o0))*64 + f)*64 + w0;
    float* op1 = outp + (((size_t)(b*31 + o0+1))*64 + f)*64 + w0;
    #pragma unroll
    for (int p=0;p<4;p++){
      float2 v = ull2f(acc[j2][p]);
      op0[p] = fmaxf(v.x + b0, 0.f);
      if (o0+1 < 31) op1[p] = fmaxf(v.y + b1, 0.f);
    }
  }
}

// ---------------------------------------------------------------------------
// Spectral fused conv-a (9x9, Cin->64, relu) + conv-b (1x1, 64->32, relu).
// Batched over all 31 branches via blockIdx.z.
// Grid: (16 tiles of 16x16, b=32, br=31). Block 256.
// conv-a: thread = (pg<32, cs<8): 8 px x 4 ch-PAIRS = 32 f32x2 accs.
//   Weights transposed in smem bigW[k*66+ch] -> LDS.64 ch-pairs; pixels dup2'd.
// ha restaged channel-major big2[ch*258+px]; conv-b: thread = (pq<64,c4<4):
//   2 px-pairs (LDS.64) x 8 out-ch, wb duplicated in smem (LDS.64 dup).
// ---------------------------------------------------------------------------
extern "C" __global__ void __launch_bounds__(256,2) spec_ab_kernel(
    const float* __restrict__ s3,
    const float* __restrict__ We1a, const float* __restrict__ be1a,
    const float* __restrict__ We1b, const float* __restrict__ be1b,
    const float* __restrict__ We2a, const float* __restrict__ be2a,
    const float* __restrict__ We2b, const float* __restrict__ be2b,
    float* __restrict__ hb_all)
{
  extern __shared__ float sm[];
  float* in_sh = sm;                   // 3*24*24 = 1728
  float* bigW  = sm + 1728;            // 16640: conv-a weights [k*66+ch], then ha [ch*258+px]
  float* wbdup = sm + 1728 + 16640;    // 32*130 duplicated wb

  const int br = blockIdx.z;
  const float *wa, *ba, *wb, *bb; int c0, Cin;
  if (br == 0){
    Cin=2; c0=0;  wa=We1a;        ba=be1a;    wb=We1b;      bb=be1b;
  } else if (br == 30){
    Cin=2; c0=29; wa=We1a+10368;  ba=be1a+64; wb=We1b+2048; bb=be1b+32;
  } else {
    int m = br-1; Cin=3; c0=m;
    wa=We2a+(size_t)m*15552; ba=be2a+(size_t)m*64;
    wb=We2b+(size_t)m*2048;  bb=be2b+(size_t)m*32;
  }
  const int Ck = Cin*81;

  const int b = blockIdx.y;
  const int tile = blockIdx.x;
  const int ty0 = (tile>>2)*16, tx0 = (tile&3)*16;
  const int t = threadIdx.x;

  for (int idx = t; idx < Cin*576; idx += 256){
    int ci = idx/576, r = idx - ci*576;
    int yy = r/24, xx = r - yy*24;
    int gy = ty0-4+yy, gx = tx0-4+xx;
    float v = 0.f;
    if ((unsigned)gy < 64u && (unsigned)gx < 64u)
      v = s3[(((size_t)(b*31 + c0 + ci))*64 + gy)*64 + gx];
    in_sh[idx] = v;
  }
  for (int idx = t; idx < 64*Ck; idx += 256){
    int ch = idx/Ck, k = idx - ch*Ck;
    bigW[k*66 + ch] = wa[idx];
  }
  for (int idx = t; idx < 2048; idx += 256){
    int c = idx>>6, k = idx&63;
    float w = wb[idx];
    wbdup[c*130 + 2*k]   = w;
    wbdup[c*130 + 2*k+1] = w;
  }
  __syncthreads();

  const int pg = t>>3, cs = t&7;
  const int y = pg>>1, xb = (pg&1)*8;

  ull acc[4][8];
  #pragma unroll
  for (int j2=0;j2<4;j2++){
    float2 bv = *(const float2*)(ba + cs*8 + 2*j2);
    ull bp = pack2(bv.x, bv.y);
    #pragma unroll
    for (int p=0;p<8;p++) acc[j2][p] = bp;
  }

  #pragma unroll 1
  for (int ci=0;ci<Cin;ci++){
    #pragma unroll 1
    for (int dy=0;dy<9;dy++){
      const float* row = in_sh + (ci*24 + y + dy)*24 + xb;
      ull rr[16];
      #pragma unroll
      for (int q=0;q<4;q++){
        float4 v4 = *(const float4*)(row + q*4);
        rr[4*q]   = dup2(v4.x); rr[4*q+1] = dup2(v4.y);
        rr[4*q+2] = dup2(v4.z); rr[4*q+3] = dup2(v4.w);
      }
      const int kbase = (ci*9+dy)*9;
      #pragma unroll
      for (int dx=0;dx<9;dx++){
        const float* wr = bigW + (kbase+dx)*66 + cs*8;
        ull w0_ = *(const ull*)(wr);
        ull w1_ = *(const ull*)(wr+2);
        ull w2_ = *(const ull*)(wr+4);
        ull w3_ = *(const ull*)(wr+6);
        #pragma unroll
        for (int p=0;p<8;p++){
          fma2(acc[0][p], w0_, rr[p+dx]);
          fma2(acc[1][p], w1_, rr[p+dx]);
          fma2(acc[2][p], w2_, rr[p+dx]);
          fma2(acc[3][p], w3_, rr[p+dx]);
        }
      }
    }
  }
  __syncthreads();   // done reading bigW; reuse buffer channel-major for ha
  float* big2 = bigW;
  #pragma unroll
  for (int j2=0;j2<4;j2++){
    int ch = cs*8 + 2*j2;
    #pragma unroll
    for (int p=0;p<8;p++){
      float2 v = ull2f(acc[j2][p]);
      int px = pg*8 + p;
      big2[ch*258 + px]     = fmaxf(v.x, 0.f);
      big2[(ch+1)*258 + px] = fmaxf(v.y, 0.f);
    }
  }
  __syncthreads();

  const int pq = t>>2, c4 = t&3;
  ull a2[8][2];
  #pragma unroll
  for (int j=0;j<8;j++){
    ull d = dup2(bb[c4*8+j]);
    a2[j][0]=d; a2[j][1]=d;
  }
  #pragma unroll 4
  for (int k=0;k<64;k++){
    const float* hrow = big2 + k*258 + pq*4;
    ull v0 = *(const ull*)(hrow);
    ull v1 = *(const ull*)(hrow+2);
    const float* wr = wbdup + (c4*8)*130 + 2*k;
    #pragma unroll
    for (int j=0;j<8;j++){
      ull wd = *(const ull*)(wr + j*130);
      fma2(a2[j][0], wd, v0);
      fma2(a2[j][1], wd, v1);
    }
  }

  float* hb = hb_all + (size_t)br * (32u*32*64*64);
  #pragma unroll
  for (int j=0;j<8;j++){
    int c = c4*8+j;
    #pragma unroll
    for (int q=0;q<2;q++){
      float2 v = ull2f(a2[j][q]);
      int px = pq*4 + 2*q;
      int yy = px>>4, xx = px&15;
      float2 st = make_float2(fmaxf(v.x,0.f), fmaxf(v.y,0.f));
      *(float2*)&hb[(((size_t)(b*32 + c))*64 + ty0+yy)*64 + tx0+xx] = st;
    }
  }
}

// ---------------------------------------------------------------------------
// Spectral conv-c (5x5, 32->1) + residual add + NHWC transpose store.
// Batched over branches via blockIdx.z. Grid: (8 tiles of 32x16, b=32, br=31).
// Block 256, 2 px/thread as one f32x2 accumulator; wc duplicated in smem.
// ---------------------------------------------------------------------------
extern "C" __global__ void __launch_bounds__(256,2) spec_c_kernel(
    const float* __restrict__ hb_all,
    const float* __restrict__ We1c, const float* __restrict__ be1c,
    const float* __restrict__ We2c, const float* __restrict__ be2c,
    const float* __restrict__ s3, float* __restrict__ outp)
{
  extern __shared__ float sm[];
  float* in_sh = sm;          // 32*20*36 = 23040
  float* wd    = sm + 23040;  // 800*2 duplicated wc

  const int br = blockIdx.z;
  const float *wc, *bc;
  if (br == 0)      { wc=We1c;                 bc=be1c;   }
  else if (br == 30){ wc=We1c+800;             bc=be1c+1; }
  else              { wc=We2c+(size_t)(br-1)*800; bc=be2c+(br-1); }
  const int cbr = br;
  const float* hb = hb_all + (size_t)br * (32u*32*64*64);

  const int b = blockIdx.y;
  const int tile = blockIdx.x;
  const int ty0 = (tile>>1)*16, tx0 = (tile&1)*32;
  const int t = threadIdx.x;

  for (int idx=t; idx<800; idx+=256){
    float w = wc[idx];
    wd[2*idx] = w; wd[2*idx+1] = w;
  }
  for (int idx=t; idx<23040; idx+=256){
    int c = idx/720, r = idx - c*720;
    int yy = r/36, xx = r - yy*36;
    int gy = ty0-2+yy, gx = tx0-2+xx;
    float v=0.f;
    if ((unsigned)gy<64u && (unsigned)gx<64u)
      v = hb[(((size_t)(b*32+c))*64+gy)*64+gx];
    in_sh[idx]=v;
  }
  __syncthreads();

  const int px0 = t*2;
  const int y = px0>>5, x = px0&31;
  ull acc = dup2(bc[0]);
  #pragma unroll 1
  for (int c=0;c<32;c++){
    #pragma unroll
    for (int dy=0;dy<5;dy++){
      const float* row = in_sh + (c*20 + y + dy)*36 + x;
      ull q0 = *(const ull*)(row);
      ull q2 = *(const ull*)(row+2);
      ull q4 = *(const ull*)(row+4);
      float2 f0 = ull2f(q0), f2v = ull2f(q2), f4 = ull2f(q4);
      ull q1 = pack2(f0.y, f2v.x);
      ull q3 = pack2(f2v.y, f4.x);
      const ull* wr = (const ull*)(wd + (c*25 + dy*5)*2);
      fma2(acc, wr[0], q0);
      fma2(acc, wr[1], q1);
      fma2(acc, wr[2], q2);
      fma2(acc, wr[3], q3);
      fma2(acc, wr[4], q4);
    }
  }
  float2 a = ull2f(acc);
  const int gy = ty0+y, gx = tx0+x;
  const float* s3p = s3 + (((size_t)(b*31+cbr))*64 + gy)*64 + gx;
  float* op = outp + (((size_t)(b*64+gy))*64 + gx)*31 + cbr;
  op[0]  = s3p[0] + a.x;
  op[31] = s3p[1] + a.y;
}

// ---------------------------------------------------------------------------
extern "C" void kernel_launch(void* const* d_in, const int* in_sizes, int n_in,
                              void* d_out, int out_size)
{
  (void)in_sizes; (void)n_in; (void)out_size;
  const float* x    = (const float*)d_in[0];
  const float* W1   = (const float*)d_in[1];
  const float* b1   = (const float*)d_in[2];
  const float* W2   = (const float*)d_in[3];
  const float* b2   = (const float*)d_in[4];
  const float* W3   = (const float*)d_in[5];
  const float* b3   = (const float*)d_in[6];
  const float* We1a = (const float*)d_in[7];
  const float* be1a = (const float*)d_in[8];
  const float* We1b = (const float*)d_in[9];
  const float* be1b = (const float*)d_in[10];
  const float* We1c = (const float*)d_in[11];
  const float* be1c = (const float*)d_in[12];
  const float* We2a = (const float*)d_in[13];
  const float* be2a = (const float*)d_in[14];
  const float* We2b = (const float*)d_in[15];
  const float* be2b = (const float*)d_in[16];
  const float* We2c = (const float*)d_in[17];
  const float* be2c = (const float*)d_in[18];

  float *s1,*s2,*s3,*hbuf;
  cudaGetSymbolAddress((void**)&s1, g_s1);
  cudaGetSymbolAddress((void**)&s2, g_s2);
  cudaGetSymbolAddress((void**)&s3, g_s3);
  cudaGetSymbolAddress((void**)&hbuf, g_hb);

  const int SPAT_SM = (4*64*66 + 192*34)*4;        // 93696 B
  const int AB_SM   = (1728 + 16640 + 32*130)*4;   // 90112 B
  const int C_SM    = (23040 + 1600)*4;            // 98560 B
  cudaFuncSetAttribute(spatial_kernel, cudaFuncAttributeMaxDynamicSharedMemorySize, SPAT_SM);
  cudaFuncSetAttribute(spec_ab_kernel, cudaFuncAttributeMaxDynamicSharedMemorySize, AB_SM);
  cudaFuncSetAttribute(spec_c_kernel,  cudaFuncAttributeMaxDynamicSharedMemorySize, C_SM);

  spatial_kernel<<<dim3(64,8),256,SPAT_SM>>>(x,  W1, b1, s1, 1);
  spatial_kernel<<<dim3(64,8),256,SPAT_SM>>>(s1, W2, b2, s2, 31);
  spatial_kernel<<<dim3(64,8),256,SPAT_SM>>>(s2, W3, b3, s3, 31);

  float* out = (float*)d_out;
  spec_ab_kernel<<<dim3(16,32,31),256,AB_SM>>>(s3, We1a,be1a,We1b,be1b,
                                               We2a,be2a,We2b,be2b, hbuf);
  spec_c_kernel<<<dim3(8,32,31),256,C_SM>>>(hbuf, We1c,be1c,We2c,be2c, s3, out);
}

// round 11
// speedup vs baseline: 1.3524x; 1.1046x over previous
#include <cuda_runtime.h>
#include <cstddef>

typedef unsigned long long ull;

// Scratch (allocation-free rule: __device__ globals)
__device__ float g_s1[32*31*64*64];
__device__ float g_s2[32*31*64*64];
__device__ float g_s3[32*31*64*64];
__device__ float g_hb[31u*32*32*64*64];   // per-branch hb, 520MB

// ---- packed f32x2 helpers -------------------------------------------------
__device__ __forceinline__ void fma2(ull& d, ull a, ull b){
  asm("fma.rn.f32x2 %0, %1, %2, %0;" : "+l"(d) : "l"(a), "l"(b));
}
__device__ __forceinline__ ull dup2(float v){
  ull r; asm("mov.b64 %0, {%1, %1};" : "=l"(r) : "f"(v)); return r;
}
__device__ __forceinline__ ull pack2(float lo, float hi){
  ull r; asm("mov.b64 %0, {%1, %2};" : "=l"(r) : "f"(lo), "f"(hi)); return r;
}
__device__ __forceinline__ float2 ull2f(ull v){
  float2 f; asm("mov.b64 {%0, %1}, %2;" : "=f"(f.x), "=f"(f.y) : "l"(v)); return f;
}

// ---------------------------------------------------------------------------
// Spatial stage: out[b][o][f][w] = relu(bias[f][o] +
//     sum_{i<Cin,kh<64,kw<3} inp[b][i][kh][w+kw-1] * W[f][o][i][kh][kw])
// Grid: (f=64, bgroup=8), block 256 = 4 b-subblocks x 64 threads.
// Thread tile: 4 o-PAIRS x 4 w => 16 f32x2 accs.
// Weights transposed in smem pitch 36 (16B aligned) -> LDS.128 o-pair loads.
// ---------------------------------------------------------------------------
extern "C" __global__ void __launch_bounds__(256,2) spatial_kernel(
    const float* __restrict__ inp, const float* __restrict__ Wt,
    const float* __restrict__ bias, float* __restrict__ outp, int Cin)
{
  extern __shared__ float sm[];
  float* s_in = sm;               // 4 * 64*66 floats (rows padded with zeros)
  float* swT  = sm + 4*64*66;     // 192*36 floats, [r][o] transposed, col 31 zero

  const int f = blockIdx.x;
  const int t = threadIdx.x;
  const int bsub = t >> 6, tl = t & 63;
  const int b = blockIdx.y*4 + bsub;
  const int ws = tl >> 2, os = tl & 3;
  const int w0 = ws*4;
  float* my_in = s_in + bsub*(64*66);

  my_in[tl*66]      = 0.f;
  my_in[tl*66 + 65] = 0.f;
  if (t < 192) swT[t*36 + 31] = 0.f;

  ull acc[4][4];
  #pragma unroll
  for (int j2=0;j2<4;j2++)
    #pragma unroll
    for (int p=0;p<4;p++) acc[j2][p] = 0ull;

  #pragma unroll 1
  for (int i=0;i<Cin;i++){
    __syncthreads();
    const float* gin = inp + ((size_t)(b*Cin + i) << 12);
    for (int idx = tl; idx < 4096; idx += 64)
      my_in[(idx>>6)*66 + 1 + (idx&63)] = gin[idx];
    for (int idx = t; idx < 31*192; idx += 256){
      int o = idx/192, r = idx - o*192;
      swT[r*36 + o] = Wt[((size_t)(f*31 + o)*Cin + i)*192 + r];
    }
    __syncthreads();

    #pragma unroll 1
    for (int kh=0; kh<64; kh++){
      const float* ir = my_in + kh*66 + w0;   // logical w0-1 .. w0+4
      float2 u0 = *(const float2*)(ir);
      float2 u1 = *(const float2*)(ir+2);
      float2 u2 = *(const float2*)(ir+4);
      ull rr[6];
      rr[0]=dup2(u0.x); rr[1]=dup2(u0.y); rr[2]=dup2(u1.x);
      rr[3]=dup2(u1.y); rr[4]=dup2(u2.x); rr[5]=dup2(u2.y);
      const float* wbp = swT + kh*108 + os*8;
      ull wp[3][4];
      #pragma unroll
      for (int ki=0;ki<3;ki++){
        ulonglong2 vA = *(const ulonglong2*)(wbp + ki*36);
        ulonglong2 vB = *(const ulonglong2*)(wbp + ki*36 + 4);
        wp[ki][0]=vA.x; wp[ki][1]=vA.y; wp[ki][2]=vB.x; wp[ki][3]=vB.y;
      }
      #pragma unroll
      for (int ki=0;ki<3;ki++)
        #pragma unroll
        for (int j2=0;j2<4;j2++)
          #pragma unroll
          for (int p=0;p<4;p++)
            fma2(acc[j2][p], wp[ki][j2], rr[p+ki]);
    }
  }

  #pragma unroll
  for (int j2=0;j2<4;j2++){
    int o0 = os*8 + 2*j2;
    float b0 = bias[f*31 + o0];
    float b1 = (o0+1 < 31) ? bias[f*31 + o0 + 1] : 0.f;
    float* op0 = outp + (((size_t)(b*31 + o0))*64 + f)*64 + w0;
    float* op1 = outp + (((size_t)(b*31 + o0+1))*64 + f)*64 + w0;
    #pragma unroll
    for (int p=0;p<4;p++){
      float2 v = ull2f(acc[j2][p]);
      op0[p] = fmaxf(v.x + b0, 0.f);
      if (o0+1 < 31) op1[p] = fmaxf(v.y + b1, 0.f);
    }
  }
}

// ---------------------------------------------------------------------------
// Spectral fused conv-a (9x9, Cin->64, relu) + conv-b (1x1, 64->32, relu).
// Batched over all 31 branches via blockIdx.z.
// Grid: (16 tiles of 16x16, b=32, br=31). Block 256.
// conv-a: thread = (pg<16: one 16-px row, cs<16: 4 ch = 2 ch-pairs).
//   32 f32x2 accs. Weights [k][gap-padded ch] pitch 68: the 16-lane LDS.64
//   set is one conflict-free 128B wavefront. Each input pixel dup'd ONCE and
//   applied to all 9 dx positions (18 weight regs live).
// ha restaged channel-major pitch 260 (16B rows); conv-b: thread = (pq<64:
//   4 px via LDS.128, c4<4: 4 ch-pairs via 2 LDS.128 from wbT[k][36]).
// ---------------------------------------------------------------------------
extern "C" __global__ void __launch_bounds__(256,2) spec_ab_kernel(
    const float* __restrict__ s3,
    const float* __restrict__ We1a, const float* __restrict__ be1a,
    const float* __restrict__ We1b, const float* __restrict__ be1b,
    const float* __restrict__ We2a, const float* __restrict__ be2a,
    const float* __restrict__ We2b, const float* __restrict__ be2b,
    float* __restrict__ hb_all)
{
  extern __shared__ float sm[];
  float* in_sh = sm;                   // 3*24*24 = 1728
  float* bigW  = sm + 1728;            // 16640: conv-a W [k*68+off(ch)], then ha [ch*260+px]
  float* wbT   = sm + 1728 + 16640;    // 64*36 transposed wb

  const int br = blockIdx.z;
  const float *wa, *ba, *wb, *bb; int c0, Cin;
  if (br == 0){
    Cin=2; c0=0;  wa=We1a;        ba=be1a;    wb=We1b;      bb=be1b;
  } else if (br == 30){
    Cin=2; c0=29; wa=We1a+10368;  ba=be1a+64; wb=We1b+2048; bb=be1b+32;
  } else {
    int m = br-1; Cin=3; c0=m;
    wa=We2a+(size_t)m*15552; ba=be2a+(size_t)m*64;
    wb=We2b+(size_t)m*2048;  bb=be2b+(size_t)m*32;
  }
  const int Ck = Cin*81;

  const int b = blockIdx.y;
  const int tile = blockIdx.x;
  const int ty0 = (tile>>2)*16, tx0 = (tile&3)*16;
  const int t = threadIdx.x;

  for (int idx = t; idx < Cin*576; idx += 256){
    int ci = idx/576, r = idx - ci*576;
    int yy = r/24, xx = r - yy*24;
    int gy = ty0-4+yy, gx = tx0-4+xx;
    float v = 0.f;
    if ((unsigned)gy < 64u && (unsigned)gx < 64u)
      v = s3[(((size_t)(b*31 + c0 + ci))*64 + gy)*64 + gx];
    in_sh[idx] = v;
  }
  // conv-a weights: bigW[k*68 + n + 2*(n>>5)]  (gap after ch 31 -> no 128B-bank hits)
  for (int idx = t; idx < 64*Ck; idx += 256){
    int n = idx/Ck, k = idx - n*Ck;
    bigW[k*68 + n + ((n>>5)<<1)] = wa[idx];
  }
  // conv-b weights transposed: wbT[k*36 + c]
  for (int idx = t; idx < 2048; idx += 256){
    int c = idx & 31, k = idx >> 5;
    wbT[k*36 + c] = wb[c*64 + k];
  }
  __syncthreads();

  const int pg = t>>4, cs = t&15;            // pg = pixel row, cs = ch-slot (4 ch)
  const int woff = cs*4 + ((cs>>3)<<1);

  ull acc[2][16];
  {
    ull bp0 = pack2(ba[cs*4],   ba[cs*4+1]);
    ull bp1 = pack2(ba[cs*4+2], ba[cs*4+3]);
    #pragma unroll
    for (int p=0;p<16;p++){ acc[0][p]=bp0; acc[1][p]=bp1; }
  }

  #pragma unroll 1
  for (int ci=0;ci<Cin;ci++){
    #pragma unroll 1
    for (int dy=0;dy<9;dy++){
      const int kbase = (ci*9+dy)*9;
      ull w[9][2];
      #pragma unroll
      for (int dx=0;dx<9;dx++){
        const float* wp_ = bigW + (kbase+dx)*68 + woff;
        w[dx][0] = *(const ull*)(wp_);
        w[dx][1] = *(const ull*)(wp_+2);
      }
      const float4* rowv = (const float4*)(in_sh + (ci*24 + pg + dy)*24);
      #pragma unroll
      for (int q=0;q<6;q++){
        float4 v4 = rowv[q];
        float rv[4] = {v4.x, v4.y, v4.z, v4.w};
        #pragma unroll
        for (int e=0;e<4;e++){
          const int p = q*4 + e;
          ull d = dup2(rv[e]);
          #pragma unroll
          for (int dx=0;dx<9;dx++){
            const int pp = p - dx;
            if (pp >= 0 && pp < 16){
              fma2(acc[0][pp], w[dx][0], d);
              fma2(acc[1][pp], w[dx][1], d);
            }
          }
        }
      }
    }
  }
  __syncthreads();   // done reading bigW; reuse as ha (channel-major pitch 260)
  float* haS = bigW;
  #pragma unroll
  for (int j=0;j<2;j++){
    int ch0 = cs*4 + 2*j;
    #pragma unroll
    for (int qg=0;qg<4;qg++){
      float4 v0, v1;
      float2 a0 = ull2f(acc[j][qg*4  ]);
      float2 a1 = ull2f(acc[j][qg*4+1]);
      float2 a2_ = ull2f(acc[j][qg*4+2]);
      float2 a3 = ull2f(acc[j][qg*4+3]);
      v0.x=fmaxf(a0.x,0.f); v0.y=fmaxf(a1.x,0.f); v0.z=fmaxf(a2_.x,0.f); v0.w=fmaxf(a3.x,0.f);
      v1.x=fmaxf(a0.y,0.f); v1.y=fmaxf(a1.y,0.f); v1.z=fmaxf(a2_.y,0.f); v1.w=fmaxf(a3.y,0.f);
      *(float4*)(haS + (ch0  )*260 + pg*16 + qg*4) = v0;
      *(float4*)(haS + (ch0+1)*260 + pg*16 + qg*4) = v1;
    }
  }
  __syncthreads();

  // ---- conv-b: thread = (pq<64: 4 px, c4<4: 8 out-ch as 4 pairs) ----
  const int pq = t >> 2, c4 = t & 3;
  ull a2[4][4];   // [ch-pair][px]
  #pragma unroll
  for (int j=0;j<4;j++){
    ull bp = pack2(bb[c4*8 + 2*j], bb[c4*8 + 2*j + 1]);
    #pragma unroll
    for (int p=0;p<4;p++) a2[j][p] = bp;
  }
  #pragma unroll 4
  for (int k=0;k<64;k++){
    float4 pv = *(const float4*)(haS + k*260 + pq*4);
    ull d0 = dup2(pv.x), d1 = dup2(pv.y), d2 = dup2(pv.z), d3 = dup2(pv.w);
    const float* wr = wbT + k*36 + c4*8;
    ulonglong2 wv0 = *(const ulonglong2*)(wr);
    ulonglong2 wv1 = *(const ulonglong2*)(wr + 4);
    fma2(a2[0][0], wv0.x, d0); fma2(a2[0][1], wv0.x, d1);
    fma2(a2[0][2], wv0.x, d2); fma2(a2[0][3], wv0.x, d3);
    fma2(a2[1][0], wv0.y, d0); fma2(a2[1][1], wv0.y, d1);
    fma2(a2[1][2], wv0.y, d2); fma2(a2[1][3], wv0.y, d3);
    fma2(a2[2][0], wv1.x, d0); fma2(a2[2][1], wv1.x, d1);
    fma2(a2[2][2], wv1.x, d2); fma2(a2[2][3], wv1.x, d3);
    fma2(a2[3][0], wv1.y, d0); fma2(a2[3][1], wv1.y, d1);
    fma2(a2[3][2], wv1.y, d2); fma2(a2[3][3], wv1.y, d3);
  }

  float* hb = hb_all + (size_t)br * (32u*32*64*64);
  const int gy = ty0 + (pq>>2), gx0 = tx0 + (pq&3)*4;
  #pragma unroll
  for (int j=0;j<4;j++){
    float2 p0 = ull2f(a2[j][0]);
    float2 p1 = ull2f(a2[j][1]);
    float2 p2 = ull2f(a2[j][2]);
    float2 p3 = ull2f(a2[j][3]);
    int ch0 = c4*8 + 2*j;
    float4 o0, o1;
    o0.x=fmaxf(p0.x,0.f); o0.y=fmaxf(p1.x,0.f); o0.z=fmaxf(p2.x,0.f); o0.w=fmaxf(p3.x,0.f);
    o1.x=fmaxf(p0.y,0.f); o1.y=fmaxf(p1.y,0.f); o1.z=fmaxf(p2.y,0.f); o1.w=fmaxf(p3.y,0.f);
    *(float4*)&hb[(((size_t)(b*32 + ch0  ))*64 + gy)*64 + gx0] = o0;
    *(float4*)&hb[(((size_t)(b*32 + ch0+1))*64 + gy)*64 + gx0] = o1;
  }
}

// ---------------------------------------------------------------------------
// Spectral conv-c (5x5, 32->1) + residual add + NHWC transpose store.
// Batched over branches via blockIdx.z. Grid: (8 tiles of 32x16, b=32, br=31).
// Block 256, 2 px/thread as one f32x2 accumulator; wc duplicated in smem.
// ---------------------------------------------------------------------------
extern "C" __global__ void __launch_bounds__(256,2) spec_c_kernel(
    const float* __restrict__ hb_all,
    const float* __restrict__ We1c, const float* __restrict__ be1c,
    const float* __restrict__ We2c, const float* __restrict__ be2c,
    const float* __restrict__ s3, float* __restrict__ outp)
{
  extern __shared__ float sm[];
  float* in_sh = sm;          // 32*20*36 = 23040
  float* wd    = sm + 23040;  // 800*2 duplicated wc

  const int br = blockIdx.z;
  const float *wc, *bc;
  if (br == 0)      { wc=We1c;                 bc=be1c;   }
  else if (br == 30){ wc=We1c+800;             bc=be1c+1; }
  else              { wc=We2c+(size_t)(br-1)*800; bc=be2c+(br-1); }
  const int cbr = br;
  const float* hb = hb_all + (size_t)br * (32u*32*64*64);

  const int b = blockIdx.y;
  const int tile = blockIdx.x;
  const int ty0 = (tile>>1)*16, tx0 = (tile&1)*32;
  const int t = threadIdx.x;

  for (int idx=t; idx<800; idx+=256){
    float w = wc[idx];
    wd[2*idx] = w; wd[2*idx+1] = w;
  }
  for (int idx=t; idx<23040; idx+=256){
    int c = idx/720, r = idx - c*720;
    int yy = r/36, xx = r - yy*36;
    int gy = ty0-2+yy, gx = tx0-2+xx;
    float v=0.f;
    if ((unsigned)gy<64u && (unsigned)gx<64u)
      v = hb[(((size_t)(b*32+c))*64+gy)*64+gx];
    in_sh[idx]=v;
  }
  __syncthreads();

  const int px0 = t*2;
  const int y = px0>>5, x = px0&31;
  ull acc = dup2(bc[0]);
  #pragma unroll 1
  for (int c=0;c<32;c++){
    #pragma unroll
    for (int dy=0;dy<5;dy++){
      const float* row = in_sh + (c*20 + y + dy)*36 + x;
      ull q0 = *(const ull*)(row);
      ull q2 = *(const ull*)(row+2);
      ull q4 = *(const ull*)(row+4);
      float2 f0 = ull2f(q0), f2v = ull2f(q2), f4 = ull2f(q4);
      ull q1 = pack2(f0.y, f2v.x);
      ull q3 = pack2(f2v.y, f4.x);
      const ull* wr = (const ull*)(wd + (c*25 + dy*5)*2);
      fma2(acc, wr[0], q0);
      fma2(acc, wr[1], q1);
      fma2(acc, wr[2], q2);
      fma2(acc, wr[3], q3);
      fma2(acc, wr[4], q4);
    }
  }
  float2 a = ull2f(acc);
  const int gy = ty0+y, gx = tx0+x;
  const float* s3p = s3 + (((size_t)(b*31+cbr))*64 + gy)*64 + gx;
  float* op = outp + (((size_t)(b*64+gy))*64 + gx)*31 + cbr;
  op[0]  = s3p[0] + a.x;
  op[31] = s3p[1] + a.y;
}

// ---------------------------------------------------------------------------
extern "C" void kernel_launch(void* const* d_in, const int* in_sizes, int n_in,
                              void* d_out, int out_size)
{
  (void)in_sizes; (void)n_in; (void)out_size;
  const float* x    = (const float*)d_in[0];
  const float* W1   = (const float*)d_in[1];
  const float* b1   = (const float*)d_in[2];
  const float* W2   = (const float*)d_in[3];
  const float* b2   = (const float*)d_in[4];
  const float* W3   = (const float*)d_in[5];
  const float* b3   = (const float*)d_in[6];
  const float* We1a = (const float*)d_in[7];
  const float* be1a = (const float*)d_in[8];
  const float* We1b = (const float*)d_in[9];
  const float* be1b = (const float*)d_in[10];
  const float* We1c = (const float*)d_in[11];
  const float* be1c = (const float*)d_in[12];
  const float* We2a = (const float*)d_in[13];
  const float* be2a = (const float*)d_in[14];
  const float* We2b = (const float*)d_in[15];
  const float* be2b = (const float*)d_in[16];
  const float* We2c = (const float*)d_in[17];
  const float* be2c = (const float*)d_in[18];

  float *s1,*s2,*s3,*hbuf;
  cudaGetSymbolAddress((void**)&s1, g_s1);
  cudaGetSymbolAddress((void**)&s2, g_s2);
  cudaGetSymbolAddress((void**)&s3, g_s3);
  cudaGetSymbolAddress((void**)&hbuf, g_hb);

  const int SPAT_SM = (4*64*66 + 192*36)*4;        // 95232 B
  const int AB_SM   = (1728 + 16640 + 64*36)*4;    // 82688 B
  const int C_SM    = (23040 + 1600)*4;            // 98560 B
  cudaFuncSetAttribute(spatial_kernel, cudaFuncAttributeMaxDynamicSharedMemorySize, SPAT_SM);
  cudaFuncSetAttribute(spec_ab_kernel, cudaFuncAttributeMaxDynamicSharedMemorySize, AB_SM);
  cudaFuncSetAttribute(spec_c_kernel,  cudaFuncAttributeMaxDynamicSharedMemorySize, C_SM);

  spatial_kernel<<<dim3(64,8),256,SPAT_SM>>>(x,  W1, b1, s1, 1);
  spatial_kernel<<<dim3(64,8),256,SPAT_SM>>>(s1, W2, b2, s2, 31);
  spatial_kernel<<<dim3(64,8),256,SPAT_SM>>>(s2, W3, b3, s3, 31);

  float* out = (float*)d_out;
  spec_ab_kernel<<<dim3(16,32,31),256,AB_SM>>>(s3, We1a,be1a,We1b,be1b,
                                               We2a,be2a,We2b,be2b, hbuf);
  spec_c_kernel<<<dim3(8,32,31),256,C_SM>>>(hbuf, We1c,be1c,We2c,be2c, s3, out);
}

// round 14
// speedup vs baseline: 1.5425x; 1.1406x over previous
#include <cuda_runtime.h>
#include <cstdint>
#include <cstddef>

typedef unsigned long long ull;

// Scratch (allocation-free rule: __device__ globals)
__device__ float g_s1[32*31*64*64];
__device__ float g_s2[32*31*64*64];
__device__ float g_s3[32*31*64*64];
__device__ float g_hb[31u*32*32*64*64];

// ---- packed f32x2 helpers ----
__device__ __forceinline__ void fma2(ull& d, ull a, ull b){
  asm("fma.rn.f32x2 %0, %1, %2, %0;" : "+l"(d) : "l"(a), "l"(b));
}
__device__ __forceinline__ ull dup2(float v){
  ull r; asm("mov.b64 %0, {%1, %1};" : "=l"(r) : "f"(v)); return r;
}
__device__ __forceinline__ ull pack2(float lo, float hi){
  ull r; asm("mov.b64 %0, {%1, %2};" : "=l"(r) : "f"(lo), "f"(hi)); return r;
}
__device__ __forceinline__ float2 ull2f(ull v){
  float2 f; asm("mov.b64 {%0, %1}, %2;" : "=f"(f.x), "=f"(f.y) : "l"(v)); return f;
}
__device__ __forceinline__ uint32_t smem_u32(const void* p){
  uint32_t a; asm("{ .reg .u64 t; cvta.to.shared.u64 t, %1; cvt.u32.u64 %0, t; }" : "=r"(a) : "l"(p)); return a;
}

// ---- mma.sync bf16 (base sm_80+ feature set: compiles for compute_103) ----
#define MMA_BF16(c0,c1,c2,c3,a0,a1,a2,a3,b0,b1) \
  asm("mma.sync.aligned.m16n8k16.row.col.f32.bf16.bf16.f32 " \
      "{%0,%1,%2,%3}, {%4,%5,%6,%7}, {%8,%9}, {%0,%1,%2,%3};" \
      : "+f"(c0),"+f"(c1),"+f"(c2),"+f"(c3) \
      : "r"(a0),"r"(a1),"r"(a2),"r"(a3),"r"(b0),"r"(b1))

#define LDSM_X4(r0,r1,r2,r3,addr) \
  asm volatile("ldmatrix.sync.aligned.m8n8.x4.shared.b16 {%0,%1,%2,%3}, [%4];" \
      : "=r"(r0),"=r"(r1),"=r"(r2),"=r"(r3) : "r"(addr))
#define LDSM_X2(r0,r1,addr) \
  asm volatile("ldmatrix.sync.aligned.m8n8.x2.shared.b16 {%0,%1}, [%2];" \
      : "=r"(r0),"=r"(r1) : "r"(addr))

// ---------------------------------------------------------------------------
// Spatial stage (unchanged R11 winner: FFMA2, LDS.128 weights, pitch 36)
// ---------------------------------------------------------------------------
extern "C" __global__ void __launch_bounds__(256,2) spatial_kernel(
    const float* __restrict__ inp, const float* __restrict__ Wt,
    const float* __restrict__ bias, float* __restrict__ outp, int Cin)
{
  extern __shared__ float sm[];
  float* s_in = sm;
  float* swT  = sm + 4*64*66;

  const int f = blockIdx.x;
  const int t = threadIdx.x;
  const int bsub = t >> 6, tl = t & 63;
  const int b = blockIdx.y*4 + bsub;
  const int ws = tl >> 2, os = tl & 3;
  const int w0 = ws*4;
  float* my_in = s_in + bsub*(64*66);

  my_in[tl*66]      = 0.f;
  my_in[tl*66 + 65] = 0.f;
  if (t < 192) swT[t*36 + 31] = 0.f;

  ull acc[4][4];
  #pragma unroll
  for (int j2=0;j2<4;j2++)
    #pragma unroll
    for (int p=0;p<4;p++) acc[j2][p] = 0ull;

  #pragma unroll 1
  for (int i=0;i<Cin;i++){
    __syncthreads();
    const float* gin = inp + ((size_t)(b*Cin + i) << 12);
    for (int idx = tl; idx < 4096; idx += 64)
      my_in[(idx>>6)*66 + 1 + (idx&63)] = gin[idx];
    for (int idx = t; idx < 31*192; idx += 256){
      int o = idx/192, r = idx - o*192;
      swT[r*36 + o] = Wt[((size_t)(f*31 + o)*Cin + i)*192 + r];
    }
    __syncthreads();

    #pragma unroll 1
    for (int kh=0; kh<64; kh++){
      const float* ir = my_in + kh*66 + w0;
      float2 u0 = *(const float2*)(ir);
      float2 u1 = *(const float2*)(ir+2);
      float2 u2 = *(const float2*)(ir+4);
      ull rr[6];
      rr[0]=dup2(u0.x); rr[1]=dup2(u0.y); rr[2]=dup2(u1.x);
      rr[3]=dup2(u1.y); rr[4]=dup2(u2.x); rr[5]=dup2(u2.y);
      const float* wbp = swT + kh*108 + os*8;
      ull wp[3][4];
      #pragma unroll
      for (int ki=0;ki<3;ki++){
        ulonglong2 vA = *(const ulonglong2*)(wbp + ki*36);
        ulonglong2 vB = *(const ulonglong2*)(wbp + ki*36 + 4);
        wp[ki][0]=vA.x; wp[ki][1]=vA.y; wp[ki][2]=vB.x; wp[ki][3]=vB.y;
      }
      #pragma unroll
      for (int ki=0;ki<3;ki++)
        #pragma unroll
        for (int j2=0;j2<4;j2++)
          #pragma unroll
          for (int p=0;p<4;p++)
            fma2(acc[j2][p], wp[ki][j2], rr[p+ki]);
    }
  }

  #pragma unroll
  for (int j2=0;j2<4;j2++){
    int o0 = os*8 + 2*j2;
    float b0 = bias[f*31 + o0];
    float b1 = (o0+1 < 31) ? bias[f*31 + o0 + 1] : 0.f;
    float* op0 = outp + (((size_t)(b*31 + o0))*64 + f)*64 + w0;
    float* op1 = outp + (((size_t)(b*31 + o0+1))*64 + f)*64 + w0;
    #pragma unroll
    for (int p=0;p<4;p++){
      float2 v = ull2f(acc[j2][p]);
      op0[p] = fmaxf(v.x + b0, 0.f);
      if (o0+1 < 31) op1[p] = fmaxf(v.y + b1, 0.f);
    }
  }
}

// ---------------------------------------------------------------------------
// Spectral conv-a via mma.sync bf16 3-pass hi/lo + conv-b FFMA2.
// Grid (16,32,31), block 256 (8 warps). GEMM per block: M=256px, N=64ch,
// K=Cin*81 chunked at 64. Warp tile M=32 x N=64.
// smem byte map (109568 total):
//   0      in_sh fp32 (Cin*576 <= 1728 fl)         6912
//   6912   sbias fp32[64]                          256
//   7168   off_tab int[256]                        1024
//   8192   wbT fp32[64][36]                        9216
//   17408  Ahi bf16[256][72] (pitch 144B)          36864
//   54272  Alo                                     36864
//   91136  Bhi bf16[64][72]                        9216
//   100352 Blo                                     9216
//   haS fp32[64][260] aliases 17408.. after MMA (66560 B)
// Pitch 72 bf16 = 36 words == 4 mod 32 -> conflict-free ldmatrix & STS.
// ---------------------------------------------------------------------------
extern "C" __global__ void __launch_bounds__(256,2) spec_ab_kernel(
    const float* __restrict__ s3,
    const float* __restrict__ We1a, const float* __restrict__ be1a,
    const float* __restrict__ We1b, const float* __restrict__ be1b,
    const float* __restrict__ We2a, const float* __restrict__ be2a,
    const float* __restrict__ We2b, const float* __restrict__ be2b,
    float* __restrict__ hb_all)
{
  extern __shared__ char smem_raw[];
  float* in_sh   = (float*)(smem_raw);
  float* sbias   = (float*)(smem_raw + 6912);
  int*   off_tab = (int*)  (smem_raw + 7168);
  float* wbT     = (float*)(smem_raw + 8192);
  uint32_t* Ahi_w = (uint32_t*)(smem_raw + 17408);
  uint32_t* Alo_w = (uint32_t*)(smem_raw + 54272);
  uint32_t* Bhi_w = (uint32_t*)(smem_raw + 91136);
  uint32_t* Blo_w = (uint32_t*)(smem_raw + 100352);
  float* haS = (float*)(smem_raw + 17408);
  const uint32_t sbase = smem_u32(smem_raw);
  const uint32_t AHI = sbase + 17408, ALO = sbase + 54272;
  const uint32_t BHI = sbase + 91136, BLO = sbase + 100352;

  const int br = blockIdx.z;
  const float *wa, *ba, *wb, *bb; int c0, Cin;
  if (br == 0){
    Cin=2; c0=0;  wa=We1a;        ba=be1a;    wb=We1b;      bb=be1b;
  } else if (br == 30){
    Cin=2; c0=29; wa=We1a+10368;  ba=be1a+64; wb=We1b+2048; bb=be1b+32;
  } else {
    int m = br-1; Cin=3; c0=m;
    wa=We2a+(size_t)m*15552; ba=be2a+(size_t)m*64;
    wb=We2b+(size_t)m*2048;  bb=be2b+(size_t)m*32;
  }
  const int Ck = Cin*81;
  const int nchunk = (Ck + 63) >> 6;   // 3 or 4

  const int b = blockIdx.y;
  const int tile = blockIdx.x;
  const int ty0 = (tile>>2)*16, tx0 = (tile&3)*16;
  const int t = threadIdx.x;
  const int w = t>>5, lane = t&31;

  // ---- prologue ----
  for (int idx = t; idx < Cin*576; idx += 256){
    int ci = idx/576, r = idx - ci*576;
    int yy = r/24, xx = r - yy*24;
    int gy = ty0-4+yy, gx = tx0-4+xx;
    float v = 0.f;
    if ((unsigned)gy < 64u && (unsigned)gx < 64u)
      v = s3[(((size_t)(b*31 + c0 + ci))*64 + gy)*64 + gx];
    in_sh[idx] = v;
  }
  if (t < 64) sbias[t] = ba[t];
  {
    int k = t;   // exactly 256 threads
    int off = -1;
    if (k < Ck){
      int ci = k/81, r = k - ci*81;
      off = ci*576 + (r/9)*24 + (r%9);
    }
    off_tab[k] = off;
  }
  for (int idx = t; idx < 2048; idx += 256){
    int c = idx & 31, k = idx >> 5;
    wbT[k*36 + c] = wb[c*64 + k];
  }

  // ---- accumulators: warp tile M=32 (2 m16) x N=64 (8 n8) ----
  float acc[2][8][4];
  #pragma unroll
  for (int mt=0;mt<2;mt++)
    #pragma unroll
    for (int nt=0;nt<8;nt++)
      #pragma unroll
      for (int q=0;q<4;q++) acc[mt][nt][q] = 0.f;

  const int pxb = w*32 + (lane>>2);
  const int kpb = lane&3;
  const int chb = w*8 + (lane>>2);

  #pragma unroll 1
  for (int c = 0; c < nchunk; c++){
    __syncthreads();   // prev chunk's mma fully done before restage
    // ---- stage A (this warp's 32 px rows) ----
    #pragma unroll
    for (int i=0;i<4;i++){
      int px = pxb + 8*i;
      int poff = (px>>4)*24 + (px&15);
      #pragma unroll
      for (int j=0;j<8;j++){
        int kp = kpb + 4*j;
        int k0 = c*64 + 2*kp;
        int o0 = off_tab[k0];
        int o1 = off_tab[k0+1];
        float v0 = (o0>=0)? in_sh[o0+poff] : 0.f;
        float v1 = (o1>=0)? in_sh[o1+poff] : 0.f;
        uint32_t u0=__float_as_uint(v0), u1=__float_as_uint(v1);
        uint32_t hp = (u0>>16) | (u1 & 0xffff0000u);
        float r0 = v0 - __uint_as_float(u0&0xffff0000u);
        float r1 = v1 - __uint_as_float(u1&0xffff0000u);
        uint32_t lp = (__float_as_uint(r0)>>16) | (__float_as_uint(r1)&0xffff0000u);
        Ahi_w[px*36+kp] = hp;
        Alo_w[px*36+kp] = lp;
      }
    }
    // ---- stage B (this warp's 8 ch rows) ----
    #pragma unroll
    for (int j=0;j<8;j++){
      int kp = kpb + 4*j;
      int k0 = c*64 + 2*kp;
      float v0 = (k0   < Ck)? wa[chb*Ck+k0]   : 0.f;
      float v1 = (k0+1 < Ck)? wa[chb*Ck+k0+1] : 0.f;
      uint32_t u0=__float_as_uint(v0), u1=__float_as_uint(v1);
      uint32_t hp = (u0>>16) | (u1 & 0xffff0000u);
      float r0 = v0 - __uint_as_float(u0&0xffff0000u);
      float r1 = v1 - __uint_as_float(u1&0xffff0000u);
      uint32_t lp = (__float_as_uint(r0)>>16) | (__float_as_uint(r1)&0xffff0000u);
      Bhi_w[chb*36+kp] = hp;
      Blo_w[chb*36+kp] = lp;
    }
    __syncthreads();

    // ---- MMA over 4 k16 tiles ----
    #pragma unroll 1
    for (int kt=0;kt<4;kt++){
      uint32_t ah[2][4], al[2][4];
      #pragma unroll
      for (int mt=0;mt<2;mt++){
        uint32_t arow = (uint32_t)(w*32 + mt*16 + (lane&15));
        uint32_t aoff = arow*144u + (uint32_t)(kt*32) + (((uint32_t)lane>>4)<<4);
        LDSM_X4(ah[mt][0],ah[mt][1],ah[mt][2],ah[mt][3], AHI + aoff);
        LDSM_X4(al[mt][0],al[mt][1],al[mt][2],al[mt][3], ALO + aoff);
      }
      #pragma unroll
      for (int nt=0;nt<8;nt++){
        uint32_t brow = (uint32_t)(nt*8 + (lane&7));
        uint32_t boff = brow*144u + (uint32_t)(kt*32) + ((((uint32_t)lane>>3)&1u)<<4);
        uint32_t bh0,bh1,bl0,bl1;
        LDSM_X2(bh0,bh1, BHI + boff);
        LDSM_X2(bl0,bl1, BLO + boff);
        #pragma unroll
        for (int mt=0;mt<2;mt++){
          MMA_BF16(acc[mt][nt][0],acc[mt][nt][1],acc[mt][nt][2],acc[mt][nt][3],
                   ah[mt][0],ah[mt][1],ah[mt][2],ah[mt][3], bh0,bh1);
          MMA_BF16(acc[mt][nt][0],acc[mt][nt][1],acc[mt][nt][2],acc[mt][nt][3],
                   ah[mt][0],ah[mt][1],ah[mt][2],ah[mt][3], bl0,bl1);
          MMA_BF16(acc[mt][nt][0],acc[mt][nt][1],acc[mt][nt][2],acc[mt][nt][3],
                   al[mt][0],al[mt][1],al[mt][2],al[mt][3], bh0,bh1);
        }
      }
    }
  }
  __syncthreads();   // all mma done everywhere before haS aliases A region

  // ---- epilogue: bias+relu -> haS channel-major (pitch 260) ----
  #pragma unroll
  for (int mt=0;mt<2;mt++){
    int r0 = w*32 + mt*16 + (lane>>2);
    #pragma unroll
    for (int nt=0;nt<8;nt++){
      int cc = nt*8 + (lane&3)*2;
      float b0v = sbias[cc], b1v = sbias[cc+1];
      haS[cc*260 + r0]        = fmaxf(acc[mt][nt][0]+b0v, 0.f);
      haS[(cc+1)*260 + r0]    = fmaxf(acc[mt][nt][1]+b1v, 0.f);
      haS[cc*260 + r0+8]      = fmaxf(acc[mt][nt][2]+b0v, 0.f);
      haS[(cc+1)*260 + r0+8]  = fmaxf(acc[mt][nt][3]+b1v, 0.f);
    }
  }
  __syncthreads();

  // ---- conv-b: thread = (pq<64: 4 px, c4<4: 8 out-ch as 4 pairs) ----
  const int pq = t >> 2, c4 = t & 3;
  ull a2[4][4];
  #pragma unroll
  for (int j=0;j<4;j++){
    ull bp = pack2(bb[c4*8 + 2*j], bb[c4*8 + 2*j + 1]);
    #pragma unroll
    for (int p=0;p<4;p++) a2[j][p] = bp;
  }
  #pragma unroll 4
  for (int k=0;k<64;k++){
    float4 pv = *(const float4*)(haS + k*260 + pq*4);
    ull d0 = dup2(pv.x), d1 = dup2(pv.y), d2 = dup2(pv.z), d3 = dup2(pv.w);
    const float* wr = wbT + k*36 + c4*8;
    ulonglong2 wv0 = *(const ulonglong2*)(wr);
    ulonglong2 wv1 = *(const ulonglong2*)(wr + 4);
    fma2(a2[0][0], wv0.x, d0); fma2(a2[0][1], wv0.x, d1);
    fma2(a2[0][2], wv0.x, d2); fma2(a2[0][3], wv0.x, d3);
    fma2(a2[1][0], wv0.y, d0); fma2(a2[1][1], wv0.y, d1);
    fma2(a2[1][2], wv0.y, d2); fma2(a2[1][3], wv0.y, d3);
    fma2(a2[2][0], wv1.x, d0); fma2(a2[2][1], wv1.x, d1);
    fma2(a2[2][2], wv1.x, d2); fma2(a2[2][3], wv1.x, d3);
    fma2(a2[3][0], wv1.y, d0); fma2(a2[3][1], wv1.y, d1);
    fma2(a2[3][2], wv1.y, d2); fma2(a2[3][3], wv1.y, d3);
  }

  float* hb = hb_all + (size_t)br * (32u*32*64*64);
  const int gy = ty0 + (pq>>2), gx0 = tx0 + (pq&3)*4;
  #pragma unroll
  for (int j=0;j<4;j++){
    float2 p0 = ull2f(a2[j][0]);
    float2 p1 = ull2f(a2[j][1]);
    float2 p2 = ull2f(a2[j][2]);
    float2 p3 = ull2f(a2[j][3]);
    int ch0 = c4*8 + 2*j;
    float4 o0, o1;
    o0.x=fmaxf(p0.x,0.f); o0.y=fmaxf(p1.x,0.f); o0.z=fmaxf(p2.x,0.f); o0.w=fmaxf(p3.x,0.f);
    o1.x=fmaxf(p0.y,0.f); o1.y=fmaxf(p1.y,0.f); o1.z=fmaxf(p2.y,0.f); o1.w=fmaxf(p3.y,0.f);
    *(float4*)&hb[(((size_t)(b*32 + ch0  ))*64 + gy)*64 + gx0] = o0;
    *(float4*)&hb[(((size_t)(b*32 + ch0+1))*64 + gy)*64 + gx0] = o1;
  }
}

// ---------------------------------------------------------------------------
// Spectral conv-c (unchanged) + residual add + NHWC transpose store.
// ---------------------------------------------------------------------------
extern "C" __global__ void __launch_bounds__(256,2) spec_c_kernel(
    const float* __restrict__ hb_all,
    const float* __restrict__ We1c, const float* __restrict__ be1c,
    const float* __restrict__ We2c, const float* __restrict__ be2c,
    const float* __restrict__ s3, float* __restrict__ outp)
{
  extern __shared__ float sm[];
  float* in_sh = sm;
  float* wd    = sm + 23040;

  const int br = blockIdx.z;
  const float *wc, *bc;
  if (br == 0)      { wc=We1c;                 bc=be1c;   }
  else if (br == 30){ wc=We1c+800;             bc=be1c+1; }
  else              { wc=We2c+(size_t)(br-1)*800; bc=be2c+(br-1); }
  const int cbr = br;
  const float* hb = hb_all + (size_t)br * (32u*32*64*64);

  const int b = blockIdx.y;
  const int tile = blockIdx.x;
  const int ty0 = (tile>>1)*16, tx0 = (tile&1)*32;
  const int t = threadIdx.x;

  for (int idx=t; idx<800; idx+=256){
    float w = wc[idx];
    wd[2*idx] = w; wd[2*idx+1] = w;
  }
  for (int idx=t; idx<23040; idx+=256){
    int c = idx/720, r = idx - c*720;
    int yy = r/36, xx = r - yy*36;
    int gy = ty0-2+yy, gx = tx0-2+xx;
    float v=0.f;
    if ((unsigned)gy<64u && (unsigned)gx<64u)
      v = hb[(((size_t)(b*32+c))*64+gy)*64+gx];
    in_sh[idx]=v;
  }
  __syncthreads();

  const int px0 = t*2;
  const int y = px0>>5, x = px0&31;
  ull acc = dup2(bc[0]);
  #pragma unroll 1
  for (int c=0;c<32;c++){
    #pragma unroll
    for (int dy=0;dy<5;dy++){
      const float* row = in_sh + (c*20 + y + dy)*36 + x;
      ull q0 = *(const ull*)(row);
      ull q2 = *(const ull*)(row+2);
      ull q4 = *(const ull*)(row+4);
      float2 f0 = ull2f(q0), f2v = ull2f(q2), f4 = ull2f(q4);
      ull q1 = pack2(f0.y, f2v.x);
      ull q3 = pack2(f2v.y, f4.x);
      const ull* wr = (const ull*)(wd + (c*25 + dy*5)*2);
      fma2(acc, wr[0], q0);
      fma2(acc, wr[1], q1);
      fma2(acc, wr[2], q2);
      fma2(acc, wr[3], q3);
      fma2(acc, wr[4], q4);
    }
  }
  float2 a = ull2f(acc);
  const int gy = ty0+y, gx = tx0+x;
  const float* s3p = s3 + (((size_t)(b*31+cbr))*64 + gy)*64 + gx;
  float* op = outp + (((size_t)(b*64+gy))*64 + gx)*31 + cbr;
  op[0]  = s3p[0] + a.x;
  op[31] = s3p[1] + a.y;
}

// ---------------------------------------------------------------------------
extern "C" void kernel_launch(void* const* d_in, const int* in_sizes, int n_in,
                              void* d_out, int out_size)
{
  (void)in_sizes; (void)n_in; (void)out_size;
  const float* x    = (const float*)d_in[0];
  const float* W1   = (const float*)d_in[1];
  const float* b1   = (const float*)d_in[2];
  const float* W2   = (const float*)d_in[3];
  const float* b2   = (const float*)d_in[4];
  const float* W3   = (const float*)d_in[5];
  const float* b3   = (const float*)d_in[6];
  const float* We1a = (const float*)d_in[7];
  const float* be1a = (const float*)d_in[8];
  const float* We1b = (const float*)d_in[9];
  const float* be1b = (const float*)d_in[10];
  const float* We1c = (const float*)d_in[11];
  const float* be1c = (const float*)d_in[12];
  const float* We2a = (const float*)d_in[13];
  const float* be2a = (const float*)d_in[14];
  const float* We2b = (const float*)d_in[15];
  const float* be2b = (const float*)d_in[16];
  const float* We2c = (const float*)d_in[17];
  const float* be2c = (const float*)d_in[18];

  float *s1,*s2,*s3,*hbuf;
  cudaGetSymbolAddress((void**)&s1, g_s1);
  cudaGetSymbolAddress((void**)&s2, g_s2);
  cudaGetSymbolAddress((void**)&s3, g_s3);
  cudaGetSymbolAddress((void**)&hbuf, g_hb);

  const int SPAT_SM = (4*64*66 + 192*36)*4;   // 95232 B
  const int AB_SM   = 109568;                 // bytes (mma staging layout)
  const int C_SM    = (23040 + 1600)*4;       // 98560 B
  cudaFuncSetAttribute(spatial_kernel, cudaFuncAttributeMaxDynamicSharedMemorySize, SPAT_SM);
  cudaFuncSetAttribute(spec_ab_kernel, cudaFuncAttributeMaxDynamicSharedMemorySize, AB_SM);
  cudaFuncSetAttribute(spec_c_kernel,  cudaFuncAttributeMaxDynamicSharedMemorySize, C_SM);

  spatial_kernel<<<dim3(64,8),256,SPAT_SM>>>(x,  W1, b1, s1, 1);
  spatial_kernel<<<dim3(64,8),256,SPAT_SM>>>(s1, W2, b2, s2, 31);
  spatial_kernel<<<dim3(64,8),256,SPAT_SM>>>(s2, W3, b3, s3, 31);

  float* out = (float*)d_out;
  spec_ab_kernel<<<dim3(16,32,31),256,AB_SM>>>(s3, We1a,be1a,We1b,be1b,
                                               We2a,be2a,We2b,be2b, hbuf);
  spec_c_kernel<<<dim3(8,32,31),256,C_SM>>>(hbuf, We1c,be1c,We2c,be2c, s3, out);
}

// round 15
// speedup vs baseline: 1.8814x; 1.2197x over previous
#include <cuda_runtime.h>
#include <cstdint>
#include <cstddef>

typedef unsigned long long ull;

// Scratch (allocation-free rule: __device__ globals)
__device__ float g_s1[32*31*64*64];
__device__ float g_s2[32*31*64*64];
__device__ float g_s3[32*31*64*64];
__device__ float g_hb[31u*32*32*64*64];

// ---- packed f32x2 helpers ----
__device__ __forceinline__ void fma2(ull& d, ull a, ull b){
  asm("fma.rn.f32x2 %0, %1, %2, %0;" : "+l"(d) : "l"(a), "l"(b));
}
__device__ __forceinline__ ull dup2(float v){
  ull r; asm("mov.b64 %0, {%1, %1};" : "=l"(r) : "f"(v)); return r;
}
__device__ __forceinline__ ull pack2(float lo, float hi){
  ull r; asm("mov.b64 %0, {%1, %2};" : "=l"(r) : "f"(lo), "f"(hi)); return r;
}
__device__ __forceinline__ float2 ull2f(ull v){
  float2 f; asm("mov.b64 {%0, %1}, %2;" : "=f"(f.x), "=f"(f.y) : "l"(v)); return f;
}
__device__ __forceinline__ uint32_t smem_u32(const void* p){
  uint32_t a; asm("{ .reg .u64 t; cvta.to.shared.u64 t, %1; cvt.u32.u64 %0, t; }" : "=r"(a) : "l"(p)); return a;
}

// ---- mma.sync bf16 (base sm_80+ features: compiles for compute_103) ----
#define MMA_BF16(c0,c1,c2,c3,a0,a1,a2,a3,b0,b1) \
  asm("mma.sync.aligned.m16n8k16.row.col.f32.bf16.bf16.f32 " \
      "{%0,%1,%2,%3}, {%4,%5,%6,%7}, {%8,%9}, {%0,%1,%2,%3};" \
      : "+f"(c0),"+f"(c1),"+f"(c2),"+f"(c3) \
      : "r"(a0),"r"(a1),"r"(a2),"r"(a3),"r"(b0),"r"(b1))

#define LDSM_X4(r0,r1,r2,r3,addr) \
  asm volatile("ldmatrix.sync.aligned.m8n8.x4.shared.b16 {%0,%1,%2,%3}, [%4];" \
      : "=r"(r0),"=r"(r1),"=r"(r2),"=r"(r3) : "r"(addr))
#define LDSM_X2(r0,r1,addr) \
  asm volatile("ldmatrix.sync.aligned.m8n8.x2.shared.b16 {%0,%1}, [%2];" \
      : "=r"(r0),"=r"(r1) : "r"(addr))

__device__ __forceinline__ void split_pair(float v0, float v1,
                                           uint32_t& hp, uint32_t& lp){
  uint32_t u0=__float_as_uint(v0), u1=__float_as_uint(v1);
  hp = (u0>>16) | (u1 & 0xffff0000u);
  float r0 = v0 - __uint_as_float(u0&0xffff0000u);
  float r1 = v1 - __uint_as_float(u1&0xffff0000u);
  lp = (__float_as_uint(r0)>>16) | (__float_as_uint(r1)&0xffff0000u);
}

// ---------------------------------------------------------------------------
// Spatial stage via mma.sync bf16 3-pass hi/lo.
// out[b][o][f][w] = relu(bias[f][o] + sum_{i,kh,kw} in[b][i][kh][w+kw-1]*W[f][o][i][kh][kw])
// GEMM per block: M=128 px (2 b x 64 w), N=64 (2 f x 32 o, o=31 zero),
// K=Cin*192, processed per-i as 3 chunks of 64 (k=kh*3+kw).
// Grid (fpair=32, bpair=16), block 256 (8 warps, warp tile M=32 x N=32).
// smem bytes (90112): in_sh fp32 2x64x66 @0 (33792) | sbias @33792 |
//   Ahi @34816 (128x144) | Alo @53248 | Bhi @71680 (64x144) | Blo @80896
// Pitch 72 bf16 = 144B (== 4 words mod 32) -> conflict-free ldmatrix/STS.
// ---------------------------------------------------------------------------
extern "C" __global__ void __launch_bounds__(256,2) spatial_kernel(
    const float* __restrict__ inp, const float* __restrict__ Wt,
    const float* __restrict__ bias, float* __restrict__ outp, int Cin)
{
  extern __shared__ char smem_raw[];
  float* in_sh = (float*)(smem_raw);
  float* sbias = (float*)(smem_raw + 33792);
  uint32_t* Ahi_w = (uint32_t*)(smem_raw + 34816);
  uint32_t* Alo_w = (uint32_t*)(smem_raw + 53248);
  uint32_t* Bhi_w = (uint32_t*)(smem_raw + 71680);
  uint32_t* Blo_w = (uint32_t*)(smem_raw + 80896);
  const uint32_t sbase = smem_u32(smem_raw);
  const uint32_t AHI = sbase + 34816, ALO = sbase + 53248;
  const uint32_t BHI = sbase + 71680, BLO = sbase + 80896;

  const int f0 = blockIdx.x*2;
  const int b0 = blockIdx.y*2;
  const int t = threadIdx.x;
  const int w = t>>5, lane = t&31;
  const int mw = w&3, nw = w>>2;

  // zero pads once (128 rows, cols 0 and 65)
  if (t < 128){ in_sh[t*66] = 0.f; in_sh[t*66+65] = 0.f; }
  if (t < 64){
    int ff = t>>5, o = t&31;
    sbias[t] = (o<31) ? bias[(f0+ff)*31+o] : 0.f;
  }

  // staging roles
  const int arow0 = w*16 + (lane>>2);       // A rows arow0, arow0+8
  const int kpb   = lane&3;                  // k-pair base
  const int chb   = w*8 + (lane>>2);         // B row (n)
  const int bff = chb>>5, bo = chb&31;
  const float* wrow_base = nullptr;
  if (bo < 31)
    wrow_base = Wt + ((size_t)((f0+bff)*31 + bo))*Cin*192;

  float acc[2][4][4];
  #pragma unroll
  for (int mt=0;mt<2;mt++)
    #pragma unroll
    for (int nt=0;nt<4;nt++)
      #pragma unroll
      for (int q=0;q<4;q++) acc[mt][nt][q] = 0.f;

  #pragma unroll 1
  for (int i=0;i<Cin;i++){
    __syncthreads();   // prev mma done; safe to reload in_sh
    // load input for both b's: in[b][i][kh][w] (4096 each)
    #pragma unroll 1
    for (int bb=0;bb<2;bb++){
      const float* gin = inp + ((size_t)((b0+bb)*Cin + i) << 12);
      for (int idx = t; idx < 4096; idx += 256)
        in_sh[bb*4224 + (idx>>6)*66 + 1 + (idx&63)] = gin[idx];
    }
    const float* wrow = wrow_base ? (wrow_base + (size_t)i*192) : nullptr;
    __syncthreads();

    #pragma unroll 1
    for (int c=0;c<3;c++){
      // ---- stage A: 2 rows x 8 k-pairs per thread ----
      #pragma unroll
      for (int ri=0;ri<2;ri++){
        int px = arow0 + 8*ri;
        const float* inb = in_sh + (px>>6)*4224 + (px&63);
        #pragma unroll
        for (int j=0;j<8;j++){
          int kp = kpb + 4*j;
          int kloc = c*64 + 2*kp;
          int kh0 = kloc/3,     kw0 = kloc - 3*kh0;
          int kh1 = (kloc+1)/3, kw1 = (kloc+1) - 3*kh1;
          float v0 = inb[kh0*66 + kw0];
          float v1 = inb[kh1*66 + kw1];
          uint32_t hp, lp; split_pair(v0, v1, hp, lp);
          Ahi_w[px*36+kp] = hp;
          Alo_w[px*36+kp] = lp;
        }
      }
      // ---- stage B: 1 row x 8 k-pairs per thread ----
      #pragma unroll
      for (int j=0;j<8;j++){
        int kp = kpb + 4*j;
        int kloc = c*64 + 2*kp;
        float v0 = wrow ? wrow[kloc]   : 0.f;
        float v1 = wrow ? wrow[kloc+1] : 0.f;
        uint32_t hp, lp; split_pair(v0, v1, hp, lp);
        Bhi_w[chb*36+kp] = hp;
        Blo_w[chb*36+kp] = lp;
      }
      __syncthreads();

      // ---- MMA over 4 k16 tiles ----
      #pragma unroll 1
      for (int kt=0;kt<4;kt++){
        uint32_t ah[2][4], al[2][4];
        #pragma unroll
        for (int mt=0;mt<2;mt++){
          uint32_t arow = (uint32_t)(mw*32 + mt*16 + (lane&15));
          uint32_t aoff = arow*144u + (uint32_t)(kt*32) + (((uint32_t)lane>>4)<<4);
          LDSM_X4(ah[mt][0],ah[mt][1],ah[mt][2],ah[mt][3], AHI + aoff);
          LDSM_X4(al[mt][0],al[mt][1],al[mt][2],al[mt][3], ALO + aoff);
        }
        #pragma unroll
        for (int nt=0;nt<4;nt++){
          uint32_t brow = (uint32_t)(nw*32 + nt*8 + (lane&7));
          uint32_t boff = brow*144u + (uint32_t)(kt*32) + ((((uint32_t)lane>>3)&1u)<<4);
          uint32_t bh0,bh1,bl0,bl1;
          LDSM_X2(bh0,bh1, BHI + boff);
          LDSM_X2(bl0,bl1, BLO + boff);
          #pragma unroll
          for (int mt=0;mt<2;mt++){
            MMA_BF16(acc[mt][nt][0],acc[mt][nt][1],acc[mt][nt][2],acc[mt][nt][3],
                     ah[mt][0],ah[mt][1],ah[mt][2],ah[mt][3], bh0,bh1);
            MMA_BF16(acc[mt][nt][0],acc[mt][nt][1],acc[mt][nt][2],acc[mt][nt][3],
                     ah[mt][0],ah[mt][1],ah[mt][2],ah[mt][3], bl0,bl1);
            MMA_BF16(acc[mt][nt][0],acc[mt][nt][1],acc[mt][nt][2],acc[mt][nt][3],
                     al[mt][0],al[mt][1],al[mt][2],al[mt][3], bh0,bh1);
          }
        }
        __syncthreads();   // keep A/B stable until all warps finish this kt? (cheap safety)
      }
    }
  }

  // ---- epilogue: bias + relu -> out[b][o][f][w] ----
  #pragma unroll
  for (int mt=0;mt<2;mt++){
    #pragma unroll
    for (int nt=0;nt<4;nt++){
      #pragma unroll
      for (int q=0;q<4;q++){
        int r  = mw*32 + mt*16 + (lane>>2) + ((q>>1)<<3);
        int cn = nw*32 + nt*8 + (lane&3)*2 + (q&1);
        int o = cn & 31;
        if (o < 31){
          int bb = r>>6, ww = r&63;
          int ff = cn>>5;
          float v = fmaxf(acc[mt][nt][q] + sbias[cn], 0.f);
          outp[(((size_t)((b0+bb)*31 + o))*64 + (f0+ff))*64 + ww] = v;
        }
      }
    }
  }
}

// ---------------------------------------------------------------------------
// Spectral conv-a via mma.sync bf16 3-pass hi/lo + conv-b FFMA2.
// (unchanged from R14 winner)
// ---------------------------------------------------------------------------
extern "C" __global__ void __launch_bounds__(256,2) spec_ab_kernel(
    const float* __restrict__ s3,
    const float* __restrict__ We1a, const float* __restrict__ be1a,
    const float* __restrict__ We1b, const float* __restrict__ be1b,
    const float* __restrict__ We2a, const float* __restrict__ be2a,
    const float* __restrict__ We2b, const float* __restrict__ be2b,
    float* __restrict__ hb_all)
{
  extern __shared__ char smem_raw[];
  float* in_sh   = (float*)(smem_raw);
  float* sbias   = (float*)(smem_raw + 6912);
  int*   off_tab = (int*)  (smem_raw + 7168);
  float* wbT     = (float*)(smem_raw + 8192);
  uint32_t* Ahi_w = (uint32_t*)(smem_raw + 17408);
  uint32_t* Alo_w = (uint32_t*)(smem_raw + 54272);
  uint32_t* Bhi_w = (uint32_t*)(smem_raw + 91136);
  uint32_t* Blo_w = (uint32_t*)(smem_raw + 100352);
  float* haS = (float*)(smem_raw + 17408);
  const uint32_t sbase = smem_u32(smem_raw);
  const uint32_t AHI = sbase + 17408, ALO = sbase + 54272;
  const uint32_t BHI = sbase + 91136, BLO = sbase + 100352;

  const int br = blockIdx.z;
  const float *wa, *ba, *wb, *bb; int c0, Cin;
  if (br == 0){
    Cin=2; c0=0;  wa=We1a;        ba=be1a;    wb=We1b;      bb=be1b;
  } else if (br == 30){
    Cin=2; c0=29; wa=We1a+10368;  ba=be1a+64; wb=We1b+2048; bb=be1b+32;
  } else {
    int m = br-1; Cin=3; c0=m;
    wa=We2a+(size_t)m*15552; ba=be2a+(size_t)m*64;
    wb=We2b+(size_t)m*2048;  bb=be2b+(size_t)m*32;
  }
  const int Ck = Cin*81;
  const int nchunk = (Ck + 63) >> 6;

  const int b = blockIdx.y;
  const int tile = blockIdx.x;
  const int ty0 = (tile>>2)*16, tx0 = (tile&3)*16;
  const int t = threadIdx.x;
  const int w = t>>5, lane = t&31;

  for (int idx = t; idx < Cin*576; idx += 256){
    int ci = idx/576, r = idx - ci*576;
    int yy = r/24, xx = r - yy*24;
    int gy = ty0-4+yy, gx = tx0-4+xx;
    float v = 0.f;
    if ((unsigned)gy < 64u && (unsigned)gx < 64u)
      v = s3[(((size_t)(b*31 + c0 + ci))*64 + gy)*64 + gx];
    in_sh[idx] = v;
  }
  if (t < 64) sbias[t] = ba[t];
  {
    int k = t;
    int off = -1;
    if (k < Ck){
      int ci = k/81, r = k - ci*81;
      off = ci*576 + (r/9)*24 + (r%9);
    }
    off_tab[k] = off;
  }
  for (int idx = t; idx < 2048; idx += 256){
    int c = idx & 31, k = idx >> 5;
    wbT[k*36 + c] = wb[c*64 + k];
  }

  float acc[2][8][4];
  #pragma unroll
  for (int mt=0;mt<2;mt++)
    #pragma unroll
    for (int nt=0;nt<8;nt++)
      #pragma unroll
      for (int q=0;q<4;q++) acc[mt][nt][q] = 0.f;

  const int pxb = w*32 + (lane>>2);
  const int kpb = lane&3;
  const int chb = w*8 + (lane>>2);

  #pragma unroll 1
  for (int c = 0; c < nchunk; c++){
    __syncthreads();
    #pragma unroll
    for (int i=0;i<4;i++){
      int px = pxb + 8*i;
      int poff = (px>>4)*24 + (px&15);
      #pragma unroll
      for (int j=0;j<8;j++){
        int kp = kpb + 4*j;
        int k0 = c*64 + 2*kp;
        int o0 = off_tab[k0];
        int o1 = off_tab[k0+1];
        float v0 = (o0>=0)? in_sh[o0+poff] : 0.f;
        float v1 = (o1>=0)? in_sh[o1+poff] : 0.f;
        uint32_t hp, lp; split_pair(v0, v1, hp, lp);
        Ahi_w[px*36+kp] = hp;
        Alo_w[px*36+kp] = lp;
      }
    }
    #pragma unroll
    for (int j=0;j<8;j++){
      int kp = kpb + 4*j;
      int k0 = c*64 + 2*kp;
      float v0 = (k0   < Ck)? wa[chb*Ck+k0]   : 0.f;
      float v1 = (k0+1 < Ck)? wa[chb*Ck+k0+1] : 0.f;
      uint32_t hp, lp; split_pair(v0, v1, hp, lp);
      Bhi_w[chb*36+kp] = hp;
      Blo_w[chb*36+kp] = lp;
    }
    __syncthreads();

    #pragma unroll 1
    for (int kt=0;kt<4;kt++){
      uint32_t ah[2][4], al[2][4];
      #pragma unroll
      for (int mt=0;mt<2;mt++){
        uint32_t arow = (uint32_t)(w*32 + mt*16 + (lane&15));
        uint32_t aoff = arow*144u + (uint32_t)(kt*32) + (((uint32_t)lane>>4)<<4);
        LDSM_X4(ah[mt][0],ah[mt][1],ah[mt][2],ah[mt][3], AHI + aoff);
        LDSM_X4(al[mt][0],al[mt][1],al[mt][2],al[mt][3], ALO + aoff);
      }
      #pragma unroll
      for (int nt=0;nt<8;nt++){
        uint32_t brow = (uint32_t)(nt*8 + (lane&7));
        uint32_t boff = brow*144u + (uint32_t)(kt*32) + ((((uint32_t)lane>>3)&1u)<<4);
        uint32_t bh0,bh1,bl0,bl1;
        LDSM_X2(bh0,bh1, BHI + boff);
        LDSM_X2(bl0,bl1, BLO + boff);
        #pragma unroll
        for (int mt=0;mt<2;mt++){
          MMA_BF16(acc[mt][nt][0],acc[mt][nt][1],acc[mt][nt][2],acc[mt][nt][3],
                   ah[mt][0],ah[mt][1],ah[mt][2],ah[mt][3], bh0,bh1);
          MMA_BF16(acc[mt][nt][0],acc[mt][nt][1],acc[mt][nt][2],acc[mt][nt][3],
                   ah[mt][0],ah[mt][1],ah[mt][2],ah[mt][3], bl0,bl1);
          MMA_BF16(acc[mt][nt][0],acc[mt][nt][1],acc[mt][nt][2],acc[mt][nt][3],
                   al[mt][0],al[mt][1],al[mt][2],al[mt][3], bh0,bh1);
        }
      }
    }
  }
  __syncthreads();

  #pragma unroll
  for (int mt=0;mt<2;mt++){
    int r0 = w*32 + mt*16 + (lane>>2);
    #pragma unroll
    for (int nt=0;nt<8;nt++){
      int cc = nt*8 + (lane&3)*2;
      float b0v = sbias[cc], b1v = sbias[cc+1];
      haS[cc*260 + r0]        = fmaxf(acc[mt][nt][0]+b0v, 0.f);
      haS[(cc+1)*260 + r0]    = fmaxf(acc[mt][nt][1]+b1v, 0.f);
      haS[cc*260 + r0+8]      = fmaxf(acc[mt][nt][2]+b0v, 0.f);
      haS[(cc+1)*260 + r0+8]  = fmaxf(acc[mt][nt][3]+b1v, 0.f);
    }
  }
  __syncthreads();

  const int pq = t >> 2, c4 = t & 3;
  ull a2[4][4];
  #pragma unroll
  for (int j=0;j<4;j++){
    ull bp = pack2(bb[c4*8 + 2*j], bb[c4*8 + 2*j + 1]);
    #pragma unroll
    for (int p=0;p<4;p++) a2[j][p] = bp;
  }
  #pragma unroll 4
  for (int k=0;k<64;k++){
    float4 pv = *(const float4*)(haS + k*260 + pq*4);
    ull d0 = dup2(pv.x), d1 = dup2(pv.y), d2 = dup2(pv.z), d3 = dup2(pv.w);
    const float* wr = wbT + k*36 + c4*8;
    ulonglong2 wv0 = *(const ulonglong2*)(wr);
    ulonglong2 wv1 = *(const ulonglong2*)(wr + 4);
    fma2(a2[0][0], wv0.x, d0); fma2(a2[0][1], wv0.x, d1);
    fma2(a2[0][2], wv0.x, d2); fma2(a2[0][3], wv0.x, d3);
    fma2(a2[1][0], wv0.y, d0); fma2(a2[1][1], wv0.y, d1);
    fma2(a2[1][2], wv0.y, d2); fma2(a2[1][3], wv0.y, d3);
    fma2(a2[2][0], wv1.x, d0); fma2(a2[2][1], wv1.x, d1);
    fma2(a2[2][2], wv1.x, d2); fma2(a2[2][3], wv1.x, d3);
    fma2(a2[3][0], wv1.y, d0); fma2(a2[3][1], wv1.y, d1);
    fma2(a2[3][2], wv1.y, d2); fma2(a2[3][3], wv1.y, d3);
  }

  float* hb = hb_all + (size_t)br * (32u*32*64*64);
  const int gy = ty0 + (pq>>2), gx0 = tx0 + (pq&3)*4;
  #pragma unroll
  for (int j=0;j<4;j++){
    float2 p0 = ull2f(a2[j][0]);
    float2 p1 = ull2f(a2[j][1]);
    float2 p2 = ull2f(a2[j][2]);
    float2 p3 = ull2f(a2[j][3]);
    int ch0 = c4*8 + 2*j;
    float4 o0, o1;
    o0.x=fmaxf(p0.x,0.f); o0.y=fmaxf(p1.x,0.f); o0.z=fmaxf(p2.x,0.f); o0.w=fmaxf(p3.x,0.f);
    o1.x=fmaxf(p0.y,0.f); o1.y=fmaxf(p1.y,0.f); o1.z=fmaxf(p2.y,0.f); o1.w=fmaxf(p3.y,0.f);
    *(float4*)&hb[(((size_t)(b*32 + ch0  ))*64 + gy)*64 + gx0] = o0;
    *(float4*)&hb[(((size_t)(b*32 + ch0+1))*64 + gy)*64 + gx0] = o1;
  }
}

// ---------------------------------------------------------------------------
// Spectral conv-c (unchanged) + residual add + NHWC transpose store.
// ---------------------------------------------------------------------------
extern "C" __global__ void __launch_bounds__(256,2) spec_c_kernel(
    const float* __restrict__ hb_all,
    const float* __restrict__ We1c, const float* __restrict__ be1c,
    const float* __restrict__ We2c, const float* __restrict__ be2c,
    const float* __restrict__ s3, float* __restrict__ outp)
{
  extern __shared__ float sm[];
  float* in_sh = sm;
  float* wd    = sm + 23040;

  const int br = blockIdx.z;
  const float *wc, *bc;
  if (br == 0)      { wc=We1c;                 bc=be1c;   }
  else if (br == 30){ wc=We1c+800;             bc=be1c+1; }
  else              { wc=We2c+(size_t)(br-1)*800; bc=be2c+(br-1); }
  const int cbr = br;
  const float* hb = hb_all + (size_t)br * (32u*32*64*64);

  const int b = blockIdx.y;
  const int tile = blockIdx.x;
  const int ty0 = (tile>>1)*16, tx0 = (tile&1)*32;
  const int t = threadIdx.x;

  for (int idx=t; idx<800; idx+=256){
    float w = wc[idx];
    wd[2*idx] = w; wd[2*idx+1] = w;
  }
  for (int idx=t; idx<23040; idx+=256){
    int c = idx/720, r = idx - c*720;
    int yy = r/36, xx = r - yy*36;
    int gy = ty0-2+yy, gx = tx0-2+xx;
    float v=0.f;
    if ((unsigned)gy<64u && (unsigned)gx<64u)
      v = hb[(((size_t)(b*32+c))*64+gy)*64+gx];
    in_sh[idx]=v;
  }
  __syncthreads();

  const int px0 = t*2;
  const int y = px0>>5, x = px0&31;
  ull acc = dup2(bc[0]);
  #pragma unroll 1
  for (int c=0;c<32;c++){
    #pragma unroll
    for (int dy=0;dy<5;dy++){
      const float* row = in_sh + (c*20 + y + dy)*36 + x;
      ull q0 = *(const ull*)(row);
      ull q2 = *(const ull*)(row+2);
      ull q4 = *(const ull*)(row+4);
      float2 f0 = ull2f(q0), f2v = ull2f(q2), f4 = ull2f(q4);
      ull q1 = pack2(f0.y, f2v.x);
      ull q3 = pack2(f2v.y, f4.x);
      const ull* wr = (const ull*)(wd + (c*25 + dy*5)*2);
      fma2(acc, wr[0], q0);
      fma2(acc, wr[1], q1);
      fma2(acc, wr[2], q2);
      fma2(acc, wr[3], q3);
      fma2(acc, wr[4], q4);
    }
  }
  float2 a = ull2f(acc);
  const int gy = ty0+y, gx = tx0+x;
  const float* s3p = s3 + (((size_t)(b*31+cbr))*64 + gy)*64 + gx;
  float* op = outp + (((size_t)(b*64+gy))*64 + gx)*31 + cbr;
  op[0]  = s3p[0] + a.x;
  op[31] = s3p[1] + a.y;
}

// ---------------------------------------------------------------------------
extern "C" void kernel_launch(void* const* d_in, const int* in_sizes, int n_in,
                              void* d_out, int out_size)
{
  (void)in_sizes; (void)n_in; (void)out_size;
  const float* x    = (const float*)d_in[0];
  const float* W1   = (const float*)d_in[1];
  const float* b1   = (const float*)d_in[2];
  const float* W2   = (const float*)d_in[3];
  const float* b2   = (const float*)d_in[4];
  const float* W3   = (const float*)d_in[5];
  const float* b3   = (const float*)d_in[6];
  const float* We1a = (const float*)d_in[7];
  const float* be1a = (const float*)d_in[8];
  const float* We1b = (const float*)d_in[9];
  const float* be1b = (const float*)d_in[10];
  const float* We1c = (const float*)d_in[11];
  const float* be1c = (const float*)d_in[12];
  const float* We2a = (const float*)d_in[13];
  const float* be2a = (const float*)d_in[14];
  const float* We2b = (const float*)d_in[15];
  const float* be2b = (const float*)d_in[16];
  const float* We2c = (const float*)d_in[17];
  const float* be2c = (const float*)d_in[18];

  float *s1,*s2,*s3,*hbuf;
  cudaGetSymbolAddress((void**)&s1, g_s1);
  cudaGetSymbolAddress((void**)&s2, g_s2);
  cudaGetSymbolAddress((void**)&s3, g_s3);
  cudaGetSymbolAddress((void**)&hbuf, g_hb);

  const int SPAT_SM = 90112;                  // bytes (mma staging layout)
  const int AB_SM   = 109568;                 // bytes (mma staging layout)
  const int C_SM    = (23040 + 1600)*4;       // 98560 B
  cudaFuncSetAttribute(spatial_kernel, cudaFuncAttributeMaxDynamicSharedMemorySize, SPAT_SM);
  cudaFuncSetAttribute(spec_ab_kernel, cudaFuncAttributeMaxDynamicSharedMemorySize, AB_SM);
  cudaFuncSetAttribute(spec_c_kernel,  cudaFuncAttributeMaxDynamicSharedMemorySize, C_SM);

  spatial_kernel<<<dim3(32,16),256,SPAT_SM>>>(x,  W1, b1, s1, 1);
  spatial_kernel<<<dim3(32,16),256,SPAT_SM>>>(s1, W2, b2, s2, 31);
  spatial_kernel<<<dim3(32,16),256,SPAT_SM>>>(s2, W3, b3, s3, 31);

  float* out = (float*)d_out;
  spec_ab_kernel<<<dim3(16,32,31),256,AB_SM>>>(s3, We1a,be1a,We1b,be1b,
                                               We2a,be2a,We2b,be2b, hbuf);
  spec_c_kernel<<<dim3(8,32,31),256,C_SM>>>(hbuf, We1c,be1c,We2c,be2c, s3, out);
}

// round 16
// speedup vs baseline: 2.0114x; 1.0691x over previous
#include <cuda_runtime.h>
#include <cstdint>
#include <cstddef>

typedef unsigned long long ull;

// Scratch (allocation-free rule: __device__ globals)
__device__ float    g_s3f[32*31*64*64];
__device__ uint32_t g_xp [32*64*64];
__device__ uint32_t g_s1p[32*31*64*64];
__device__ uint32_t g_s2p[32*31*64*64];
__device__ uint32_t g_s3p[32*31*64*64];
__device__ uint32_t g_W1p[64*31*192];
__device__ uint32_t g_W2p[64*31*31*192];
__device__ uint32_t g_W3p[64*31*31*192];
__device__ uint32_t g_wa1p[2*64*162];
__device__ uint32_t g_wa2p[29*64*243];
__device__ float    g_hb[31u*32*32*64*64];   // per-branch hb, 520MB

// ---- packed f32x2 helpers (conv-b / spec_c) ----
__device__ __forceinline__ void fma2(ull& d, ull a, ull b){
  asm("fma.rn.f32x2 %0, %1, %2, %0;" : "+l"(d) : "l"(a), "l"(b));
}
__device__ __forceinline__ ull dup2(float v){
  ull r; asm("mov.b64 %0, {%1, %1};" : "=l"(r) : "f"(v)); return r;
}
__device__ __forceinline__ ull pack2(float lo, float hi){
  ull r; asm("mov.b64 %0, {%1, %2};" : "=l"(r) : "f"(lo), "f"(hi)); return r;
}
__device__ __forceinline__ float2 ull2f(ull v){
  float2 f; asm("mov.b64 {%0, %1}, %2;" : "=f"(f.x), "=f"(f.y) : "l"(v)); return f;
}
__device__ __forceinline__ uint32_t smem_u32(const void* p){
  uint32_t a; asm("{ .reg .u64 t; cvta.to.shared.u64 t, %1; cvt.u32.u64 %0, t; }" : "=r"(a) : "l"(p)); return a;
}

// ---- mma.sync bf16 (base sm_80+ features: compiles for compute_103) ----
#define MMA_BF16(c0,c1,c2,c3,a0,a1,a2,a3,b0,b1) \
  asm("mma.sync.aligned.m16n8k16.row.col.f32.bf16.bf16.f32 " \
      "{%0,%1,%2,%3}, {%4,%5,%6,%7}, {%8,%9}, {%0,%1,%2,%3};" \
      : "+f"(c0),"+f"(c1),"+f"(c2),"+f"(c3) \
      : "r"(a0),"r"(a1),"r"(a2),"r"(a3),"r"(b0),"r"(b1))

#define LDSM_X4(r0,r1,r2,r3,addr) \
  asm volatile("ldmatrix.sync.aligned.m8n8.x4.shared.b16 {%0,%1,%2,%3}, [%4];" \
      : "=r"(r0),"=r"(r1),"=r"(r2),"=r"(r3) : "r"(addr))
#define LDSM_X2(r0,r1,addr) \
  asm volatile("ldmatrix.sync.aligned.m8n8.x2.shared.b16 {%0,%1}, [%2];" \
      : "=r"(r0),"=r"(r1) : "r"(addr))

// packed u32 = (bf16_hi << 16) | bf16_lo  (truncation split, same numerics as before)
__device__ __forceinline__ uint32_t pack_split(float v){
  uint32_t u = __float_as_uint(v);
  uint32_t hi = u & 0xffff0000u;
  float r = v - __uint_as_float(hi);
  return hi | (__float_as_uint(r) >> 16);
}
// (pk0, pk1) -> hp = {bf16: hi0 lo-half, hi1 hi-half}, lp likewise for lo parts
__device__ __forceinline__ void unpack_pair(uint32_t pk0, uint32_t pk1,
                                            uint32_t& hp, uint32_t& lp){
  asm("prmt.b32 %0, %1, %2, 0x7632;" : "=r"(hp) : "r"(pk0), "r"(pk1));
  asm("prmt.b32 %0, %1, %2, 0x5410;" : "=r"(lp) : "r"(pk0), "r"(pk1));
}

// ---------------------------------------------------------------------------
// Pre-pass: pack fp32 array -> packed split u32 array.
// ---------------------------------------------------------------------------
extern "C" __global__ void pack_split_kernel(const float* __restrict__ src,
                                             uint32_t* __restrict__ dst, int n){
  int i = blockIdx.x*blockDim.x + threadIdx.x;
  int stride = gridDim.x*blockDim.x;
  for (; i < n; i += stride) dst[i] = pack_split(src[i]);
}

// ---------------------------------------------------------------------------
// Spatial stage via mma.sync bf16 3-pass hi/lo, packed-split I/O.
// GEMM per block: M=128 px (2 b x 64 w), N=64 (2 f x 32 o, o=31 zero),
// K=Cin*192 as 3 chunks of 64 per i. Grid (fpair=32, bpair=16), block 256.
// smem: in_pk u32 2x64x66 @0 (33792) | sbias @33792 (256) | off_tab @34048 (768)
//   Ahi @34816 (128x144B) | Alo @53248 | Bhi @71680 (64x144B) | Blo @80896 (end 90112)
// ---------------------------------------------------------------------------
extern "C" __global__ void __launch_bounds__(256,2) spatial_kernel(
    const uint32_t* __restrict__ inp, const uint32_t* __restrict__ Wp,
    const float* __restrict__ bias, uint32_t* __restrict__ outp,
    float* __restrict__ outf, int Cin)
{
  extern __shared__ char smem_raw[];
  uint32_t* in_pk = (uint32_t*)smem_raw;
  float* sbias    = (float*)(smem_raw + 33792);
  int*   off_tab  = (int*)  (smem_raw + 34048);
  uint32_t* Ahi_w = (uint32_t*)(smem_raw + 34816);
  uint32_t* Alo_w = (uint32_t*)(smem_raw + 53248);
  uint32_t* Bhi_w = (uint32_t*)(smem_raw + 71680);
  uint32_t* Blo_w = (uint32_t*)(smem_raw + 80896);
  const uint32_t sbase = smem_u32(smem_raw);
  const uint32_t AHI = sbase + 34816, ALO = sbase + 53248;
  const uint32_t BHI = sbase + 71680, BLO = sbase + 80896;

  const int f0 = blockIdx.x*2;
  const int b0 = blockIdx.y*2;
  const int t = threadIdx.x;
  const int w = t>>5, lane = t&31;
  const int mw = w&3, nw = w>>2;

  if (t < 128){ in_pk[t*66] = 0u; in_pk[t*66+65] = 0u; }
  if (t < 64){
    int ff = t>>5, o = t&31;
    sbias[t] = (o<31) ? bias[(f0+ff)*31+o] : 0.f;
  }
  if (t < 192) off_tab[t] = (t/3)*66 + (t%3);

  const int arow0 = w*16 + (lane>>2);
  const int kpb   = lane&3;
  const int chb   = w*8 + (lane>>2);
  const int bff = chb>>5, bo = chb&31;
  const uint32_t* wrow_base = nullptr;
  if (bo < 31)
    wrow_base = Wp + ((size_t)((f0+bff)*31 + bo))*Cin*192;

  float acc[2][4][4];
  #pragma unroll
  for (int mt=0;mt<2;mt++)
    #pragma unroll
    for (int nt=0;nt<4;nt++)
      #pragma unroll
      for (int q=0;q<4;q++) acc[mt][nt][q] = 0.f;

  #pragma unroll 1
  for (int i=0;i<Cin;i++){
    #pragma unroll 1
    for (int bb=0;bb<2;bb++){
      const uint32_t* gin = inp + ((size_t)((b0+bb)*Cin + i) << 12);
      for (int idx = t; idx < 4096; idx += 256)
        in_pk[bb*4224 + (idx>>6)*66 + 1 + (idx&63)] = gin[idx];
    }
    const uint32_t* wrow = wrow_base ? (wrow_base + (size_t)i*192) : nullptr;
    __syncthreads();

    #pragma unroll 1
    for (int c=0;c<3;c++){
      // ---- stage A: 2 rows x 8 k-pairs per thread ----
      #pragma unroll
      for (int ri=0;ri<2;ri++){
        int px = arow0 + 8*ri;
        const uint32_t* inb = in_pk + (px>>6)*4224 + (px&63);
        #pragma unroll
        for (int j=0;j<8;j++){
          int kp = kpb + 4*j;
          int kloc = c*64 + 2*kp;
          uint32_t pk0 = inb[off_tab[kloc]];
          uint32_t pk1 = inb[off_tab[kloc+1]];
          uint32_t hp, lp; unpack_pair(pk0, pk1, hp, lp);
          Ahi_w[px*36+kp] = hp;
          Alo_w[px*36+kp] = lp;
        }
      }
      // ---- stage B: 1 row x 8 k-pairs per thread (LDG.64, kloc even) ----
      #pragma unroll
      for (int j=0;j<8;j++){
        int kp = kpb + 4*j;
        int kloc = c*64 + 2*kp;
        uint32_t pk0 = 0u, pk1 = 0u;
        if (wrow){
          ull v2 = *(const ull*)(wrow + kloc);
          pk0 = (uint32_t)v2; pk1 = (uint32_t)(v2>>32);
        }
        uint32_t hp, lp; unpack_pair(pk0, pk1, hp, lp);
        Bhi_w[chb*36+kp] = hp;
        Blo_w[chb*36+kp] = lp;
      }
      __syncthreads();

      // ---- MMA over 4 k16 tiles (no inner syncs) ----
      #pragma unroll 1
      for (int kt=0;kt<4;kt++){
        uint32_t ah[2][4], al[2][4];
        #pragma unroll
        for (int mt=0;mt<2;mt++){
          uint32_t arow = (uint32_t)(mw*32 + mt*16 + (lane&15));
          uint32_t aoff = arow*144u + (uint32_t)(kt*32) + (((uint32_t)lane>>4)<<4);
          LDSM_X4(ah[mt][0],ah[mt][1],ah[mt][2],ah[mt][3], AHI + aoff);
          LDSM_X4(al[mt][0],al[mt][1],al[mt][2],al[mt][3], ALO + aoff);
        }
        #pragma unroll
        for (int nt=0;nt<4;nt++){
          uint32_t brow = (uint32_t)(nw*32 + nt*8 + (lane&7));
          uint32_t boff = brow*144u + (uint32_t)(kt*32) + ((((uint32_t)lane>>3)&1u)<<4);
          uint32_t bh0,bh1,bl0,bl1;
          LDSM_X2(bh0,bh1, BHI + boff);
          LDSM_X2(bl0,bl1, BLO + boff);
          #pragma unroll
          for (int mt=0;mt<2;mt++){
            MMA_BF16(acc[mt][nt][0],acc[mt][nt][1],acc[mt][nt][2],acc[mt][nt][3],
                     ah[mt][0],ah[mt][1],ah[mt][2],ah[mt][3], bh0,bh1);
            MMA_BF16(acc[mt][nt][0],acc[mt][nt][1],acc[mt][nt][2],acc[mt][nt][3],
                     ah[mt][0],ah[mt][1],ah[mt][2],ah[mt][3], bl0,bl1);
            MMA_BF16(acc[mt][nt][0],acc[mt][nt][1],acc[mt][nt][2],acc[mt][nt][3],
                     al[mt][0],al[mt][1],al[mt][2],al[mt][3], bh0,bh1);
          }
        }
      }
      __syncthreads();   // A/B (and in_pk via ordering) safe to rewrite
    }
  }

  // ---- epilogue: bias + relu -> packed out (+ optional fp32) ----
  #pragma unroll
  for (int mt=0;mt<2;mt++){
    #pragma unroll
    for (int nt=0;nt<4;nt++){
      #pragma unroll
      for (int q=0;q<4;q++){
        int r  = mw*32 + mt*16 + (lane>>2) + ((q>>1)<<3);
        int cn = nw*32 + nt*8 + (lane&3)*2 + (q&1);
        int o = cn & 31;
        if (o < 31){
          int bb = r>>6, ww = r&63;
          int ff = cn>>5;
          float v = fmaxf(acc[mt][nt][q] + sbias[cn], 0.f);
          size_t idx = (((size_t)((b0+bb)*31 + o))*64 + (f0+ff))*64 + ww;
          outp[idx] = pack_split(v);
          if (outf) outf[idx] = v;
        }
      }
    }
  }
}

// ---------------------------------------------------------------------------
// Spectral conv-a via mma.sync bf16 3-pass hi/lo (packed-split inputs)
// + conv-b FFMA2. Grid (16,32,31), block 256. Layout as R14/R15 winner.
// ---------------------------------------------------------------------------
extern "C" __global__ void __launch_bounds__(256,2) spec_ab_kernel(
    const uint32_t* __restrict__ s3p,
    const uint32_t* __restrict__ wa1p, const float* __restrict__ be1a,
    const float* __restrict__ We1b, const float* __restrict__ be1b,
    const uint32_t* __restrict__ wa2p, const float* __restrict__ be2a,
    const float* __restrict__ We2b, const float* __restrict__ be2b,
    float* __restrict__ hb_all)
{
  extern __shared__ char smem_raw[];
  uint32_t* in_pk = (uint32_t*)(smem_raw);
  float* sbias   = (float*)(smem_raw + 6912);
  int*   off_tab = (int*)  (smem_raw + 7168);
  float* wbT     = (float*)(smem_raw + 8192);
  uint32_t* Ahi_w = (uint32_t*)(smem_raw + 17408);
  uint32_t* Alo_w = (uint32_t*)(smem_raw + 54272);
  uint32_t* Bhi_w = (uint32_t*)(smem_raw + 91136);
  uint32_t* Blo_w = (uint32_t*)(smem_raw + 100352);
  float* haS = (float*)(smem_raw + 17408);
  const uint32_t sbase = smem_u32(smem_raw);
  const uint32_t AHI = sbase + 17408, ALO = sbase + 54272;
  const uint32_t BHI = sbase + 91136, BLO = sbase + 100352;

  const int br = blockIdx.z;
  const uint32_t* wap; const float *ba, *wb, *bb; int c0, Cin;
  if (br == 0){
    Cin=2; c0=0;  wap=wa1p;        ba=be1a;    wb=We1b;      bb=be1b;
  } else if (br == 30){
    Cin=2; c0=29; wap=wa1p+10368;  ba=be1a+64; wb=We1b+2048; bb=be1b+32;
  } else {
    int m = br-1; Cin=3; c0=m;
    wap=wa2p+(size_t)m*15552; ba=be2a+(size_t)m*64;
    wb=We2b+(size_t)m*2048;   bb=be2b+(size_t)m*32;
  }
  const int Ck = Cin*81;
  const int nchunk = (Ck + 63) >> 6;

  const int b = blockIdx.y;
  const int tile = blockIdx.x;
  const int ty0 = (tile>>2)*16, tx0 = (tile&3)*16;
  const int t = threadIdx.x;
  const int w = t>>5, lane = t&31;

  for (int idx = t; idx < Cin*576; idx += 256){
    int ci = idx/576, r = idx - ci*576;
    int yy = r/24, xx = r - yy*24;
    int gy = ty0-4+yy, gx = tx0-4+xx;
    uint32_t v = 0u;
    if ((unsigned)gy < 64u && (unsigned)gx < 64u)
      v = s3p[(((size_t)(b*31 + c0 + ci))*64 + gy)*64 + gx];
    in_pk[idx] = v;
  }
  if (t < 64) sbias[t] = ba[t];
  {
    int k = t;
    int off = -1;
    if (k < Ck){
      int ci = k/81, r = k - ci*81;
      off = ci*576 + (r/9)*24 + (r%9);
    }
    off_tab[k] = off;
  }
  for (int idx = t; idx < 2048; idx += 256){
    int c = idx & 31, k = idx >> 5;
    wbT[k*36 + c] = wb[c*64 + k];
  }

  float acc[2][8][4];
  #pragma unroll
  for (int mt=0;mt<2;mt++)
    #pragma unroll
    for (int nt=0;nt<8;nt++)
      #pragma unroll
      for (int q=0;q<4;q++) acc[mt][nt][q] = 0.f;

  const int pxb = w*32 + (lane>>2);
  const int kpb = lane&3;
  const int chb = w*8 + (lane>>2);

  #pragma unroll 1
  for (int c = 0; c < nchunk; c++){
    __syncthreads();
    #pragma unroll
    for (int i=0;i<4;i++){
      int px = pxb + 8*i;
      int poff = (px>>4)*24 + (px&15);
      #pragma unroll
      for (int j=0;j<8;j++){
        int kp = kpb + 4*j;
        int k0 = c*64 + 2*kp;
        int o0 = off_tab[k0];
        int o1 = off_tab[k0+1];
        uint32_t pk0 = (o0>=0)? in_pk[o0+poff] : 0u;
        uint32_t pk1 = (o1>=0)? in_pk[o1+poff] : 0u;
        uint32_t hp, lp; unpack_pair(pk0, pk1, hp, lp);
        Ahi_w[px*36+kp] = hp;
        Alo_w[px*36+kp] = lp;
      }
    }
    #pragma unroll
    for (int j=0;j<8;j++){
      int kp = kpb + 4*j;
      int k0 = c*64 + 2*kp;
      uint32_t pk0 = (k0   < Ck)? wap[chb*Ck+k0]   : 0u;
      uint32_t pk1 = (k0+1 < Ck)? wap[chb*Ck+k0+1] : 0u;
      uint32_t hp, lp; unpack_pair(pk0, pk1, hp, lp);
      Bhi_w[chb*36+kp] = hp;
      Blo_w[chb*36+kp] = lp;
    }
    __syncthreads();

    #pragma unroll 1
    for (int kt=0;kt<4;kt++){
      uint32_t ah[2][4], al[2][4];
      #pragma unroll
      for (int mt=0;mt<2;mt++){
        uint32_t arow = (uint32_t)(w*32 + mt*16 + (lane&15));
        uint32_t aoff = arow*144u + (uint32_t)(kt*32) + (((uint32_t)lane>>4)<<4);
        LDSM_X4(ah[mt][0],ah[mt][1],ah[mt][2],ah[mt][3], AHI + aoff);
        LDSM_X4(al[mt][0],al[mt][1],al[mt][2],al[mt][3], ALO + aoff);
      }
      #pragma unroll
      for (int nt=0;nt<8;nt++){
        uint32_t brow = (uint32_t)(nt*8 + (lane&7));
        uint32_t boff = brow*144u + (uint32_t)(kt*32) + ((((uint32_t)lane>>3)&1u)<<4);
        uint32_t bh0,bh1,bl0,bl1;
        LDSM_X2(bh0,bh1, BHI + boff);
        LDSM_X2(bl0,bl1, BLO + boff);
        #pragma unroll
        for (int mt=0;mt<2;mt++){
          MMA_BF16(acc[mt][nt][0],acc[mt][nt][1],acc[mt][nt][2],acc[mt][nt][3],
                   ah[mt][0],ah[mt][1],ah[mt][2],ah[mt][3], bh0,bh1);
          MMA_BF16(acc[mt][nt][0],acc[mt][nt][1],acc[mt][nt][2],acc[mt][nt][3],
                   ah[mt][0],ah[mt][1],ah[mt][2],ah[mt][3], bl0,bl1);
          MMA_BF16(acc[mt][nt][0],acc[mt][nt][1],acc[mt][nt][2],acc[mt][nt][3],
                   al[mt][0],al[mt][1],al[mt][2],al[mt][3], bh0,bh1);
        }
      }
    }
  }
  __syncthreads();

  // ---- epilogue: bias+relu -> haS channel-major (pitch 260) ----
  #pragma unroll
  for (int mt=0;mt<2;mt++){
    int r0 = w*32 + mt*16 + (lane>>2);
    #pragma unroll
    for (int nt=0;nt<8;nt++){
      int cc = nt*8 + (lane&3)*2;
      float b0v = sbias[cc], b1v = sbias[cc+1];
      haS[cc*260 + r0]        = fmaxf(acc[mt][nt][0]+b0v, 0.f);
      haS[(cc+1)*260 + r0]    = fmaxf(acc[mt][nt][1]+b1v, 0.f);
      haS[cc*260 + r0+8]      = fmaxf(acc[mt][nt][2]+b0v, 0.f);
      haS[(cc+1)*260 + r0+8]  = fmaxf(acc[mt][nt][3]+b1v, 0.f);
    }
  }
  __syncthreads();

  // ---- conv-b: thread = (pq<64: 4 px, c4<4: 8 out-ch as 4 pairs) ----
  const int pq = t >> 2, c4 = t & 3;
  ull a2[4][4];
  #pragma unroll
  for (int j=0;j<4;j++){
    ull bp = pack2(bb[c4*8 + 2*j], bb[c4*8 + 2*j + 1]);
    #pragma unroll
    for (int p=0;p<4;p++) a2[j][p] = bp;
  }
  #pragma unroll 4
  for (int k=0;k<64;k++){
    float4 pv = *(const float4*)(haS + k*260 + pq*4);
    ull d0 = dup2(pv.x), d1 = dup2(pv.y), d2 = dup2(pv.z), d3 = dup2(pv.w);
    const float* wr = wbT + k*36 + c4*8;
    ulonglong2 wv0 = *(const ulonglong2*)(wr);
    ulonglong2 wv1 = *(const ulonglong2*)(wr + 4);
    fma2(a2[0][0], wv0.x, d0); fma2(a2[0][1], wv0.x, d1);
    fma2(a2[0][2], wv0.x, d2); fma2(a2[0][3], wv0.x, d3);
    fma2(a2[1][0], wv0.y, d0); fma2(a2[1][1], wv0.y, d1);
    fma2(a2[1][2], wv0.y, d2); fma2(a2[1][3], wv0.y, d3);
    fma2(a2[2][0], wv1.x, d0); fma2(a2[2][1], wv1.x, d1);
    fma2(a2[2][2], wv1.x, d2); fma2(a2[2][3], wv1.x, d3);
    fma2(a2[3][0], wv1.y, d0); fma2(a2[3][1], wv1.y, d1);
    fma2(a2[3][2], wv1.y, d2); fma2(a2[3][3], wv1.y, d3);
  }

  float* hb = hb_all + (size_t)br * (32u*32*64*64);
  const int gy = ty0 + (pq>>2), gx0 = tx0 + (pq&3)*4;
  #pragma unroll
  for (int j=0;j<4;j++){
    float2 p0 = ull2f(a2[j][0]);
    float2 p1 = ull2f(a2[j][1]);
    float2 p2 = ull2f(a2[j][2]);
    float2 p3 = ull2f(a2[j][3]);
    int ch0 = c4*8 + 2*j;
    float4 o0, o1;
    o0.x=fmaxf(p0.x,0.f); o0.y=fmaxf(p1.x,0.f); o0.z=fmaxf(p2.x,0.f); o0.w=fmaxf(p3.x,0.f);
    o1.x=fmaxf(p0.y,0.f); o1.y=fmaxf(p1.y,0.f); o1.z=fmaxf(p2.y,0.f); o1.w=fmaxf(p3.y,0.f);
    *(float4*)&hb[(((size_t)(b*32 + ch0  ))*64 + gy)*64 + gx0] = o0;
    *(float4*)&hb[(((size_t)(b*32 + ch0+1))*64 + gy)*64 + gx0] = o1;
  }
}

// ---------------------------------------------------------------------------
// Spectral conv-c (unchanged) + residual add + NHWC transpose store.
// ---------------------------------------------------------------------------
extern "C" __global__ void __launch_bounds__(256,2) spec_c_kernel(
    const float* __restrict__ hb_all,
    const float* __restrict__ We1c, const float* __restrict__ be1c,
    const float* __restrict__ We2c, const float* __restrict__ be2c,
    const float* __restrict__ s3, float* __restrict__ outp)
{
  extern __shared__ float sm[];
  float* in_sh = sm;
  float* wd    = sm + 23040;

  const int br = blockIdx.z;
  const float *wc, *bc;
  if (br == 0)      { wc=We1c;                 bc=be1c;   }
  else if (br == 30){ wc=We1c+800;             bc=be1c+1; }
  else              { wc=We2c+(size_t)(br-1)*800; bc=be2c+(br-1); }
  const int cbr = br;
  const float* hb = hb_all + (size_t)br * (32u*32*64*64);

  const int b = blockIdx.y;
  const int tile = blockIdx.x;
  const int ty0 = (tile>>1)*16, tx0 = (tile&1)*32;
  const int t = threadIdx.x;

  for (int idx=t; idx<800; idx+=256){
    float w = wc[idx];
    wd[2*idx] = w; wd[2*idx+1] = w;
  }
  for (int idx=t; idx<23040; idx+=256){
    int c = idx/720, r = idx - c*720;
    int yy = r/36, xx = r - yy*36;
    int gy = ty0-2+yy, gx = tx0-2+xx;
    float v=0.f;
    if ((unsigned)gy<64u && (unsigned)gx<64u)
      v = hb[(((size_t)(b*32+c))*64+gy)*64+gx];
    in_sh[idx]=v;
  }
  __syncthreads();

  const int px0 = t*2;
  const int y = px0>>5, x = px0&31;
  ull acc = dup2(bc[0]);
  #pragma unroll 1
  for (int c=0;c<32;c++){
    #pragma unroll
    for (int dy=0;dy<5;dy++){
      const float* row = in_sh + (c*20 + y + dy)*36 + x;
      ull q0 = *(const ull*)(row);
      ull q2 = *(const ull*)(row+2);
      ull q4 = *(const ull*)(row+4);
      float2 f0 = ull2f(q0), f2v = ull2f(q2), f4 = ull2f(q4);
      ull q1 = pack2(f0.y, f2v.x);
      ull q3 = pack2(f2v.y, f4.x);
      const ull* wr = (const ull*)(wd + (c*25 + dy*5)*2);
      fma2(acc, wr[0], q0);
      fma2(acc, wr[1], q1);
      fma2(acc, wr[2], q2);
      fma2(acc, wr[3], q3);
      fma2(acc, wr[4], q4);
    }
  }
  float2 a = ull2f(acc);
  const int gy = ty0+y, gx = tx0+x;
  const float* s3p = s3 + (((size_t)(b*31+cbr))*64 + gy)*64 + gx;
  float* op = outp + (((size_t)(b*64+gy))*64 + gx)*31 + cbr;
  op[0]  = s3p[0] + a.x;
  op[31] = s3p[1] + a.y;
}

// ---------------------------------------------------------------------------
extern "C" void kernel_launch(void* const* d_in, const int* in_sizes, int n_in,
                              void* d_out, int out_size)
{
  (void)in_sizes; (void)n_in; (void)out_size;
  const float* x    = (const float*)d_in[0];
  const float* W1   = (const float*)d_in[1];
  const float* b1   = (const float*)d_in[2];
  const float* W2   = (const float*)d_in[3];
  const float* b2   = (const float*)d_in[4];
  const float* W3   = (const float*)d_in[5];
  const float* b3   = (const float*)d_in[6];
  const float* We1a = (const float*)d_in[7];
  const float* be1a = (const float*)d_in[8];
  const float* We1b = (const float*)d_in[9];
  const float* be1b = (const float*)d_in[10];
  const float* We1c = (const float*)d_in[11];
  const float* be1c = (const float*)d_in[12];
  const float* We2a = (const float*)d_in[13];
  const float* be2a = (const float*)d_in[14];
  const float* We2b = (const float*)d_in[15];
  const float* be2b = (const float*)d_in[16];
  const float* We2c = (const float*)d_in[17];
  const float* be2c = (const float*)d_in[18];

  float *s3f, *hbuf;
  uint32_t *xp,*s1p,*s2p,*s3p,*w1p,*w2p,*w3p,*wa1p,*wa2p;
  cudaGetSymbolAddress((void**)&s3f,  g_s3f);
  cudaGetSymbolAddress((void**)&hbuf, g_hb);
  cudaGetSymbolAddress((void**)&xp,   g_xp);
  cudaGetSymbolAddress((void**)&s1p,  g_s1p);
  cudaGetSymbolAddress((void**)&s2p,  g_s2p);
  cudaGetSymbolAddress((void**)&s3p,  g_s3p);
  cudaGetSymbolAddress((void**)&w1p,  g_W1p);
  cudaGetSymbolAddress((void**)&w2p,  g_W2p);
  cudaGetSymbolAddress((void**)&w3p,  g_W3p);
  cudaGetSymbolAddress((void**)&wa1p, g_wa1p);
  cudaGetSymbolAddress((void**)&wa2p, g_wa2p);

  const int SPAT_SM = 90112;
  const int AB_SM   = 109568;
  const int C_SM    = (23040 + 1600)*4;
  cudaFuncSetAttribute(spatial_kernel, cudaFuncAttributeMaxDynamicSharedMemorySize, SPAT_SM);
  cudaFuncSetAttribute(spec_ab_kernel, cudaFuncAttributeMaxDynamicSharedMemorySize, AB_SM);
  cudaFuncSetAttribute(spec_c_kernel,  cudaFuncAttributeMaxDynamicSharedMemorySize, C_SM);

  // ---- pre-pass: pack fp32 -> split u32 (x and all MMA weights) ----
  pack_split_kernel<<<512, 256>>>(x,    xp,   32*64*64);
  pack_split_kernel<<<512, 256>>>(W1,   w1p,  64*31*192);
  pack_split_kernel<<<4096,256>>>(W2,   w2p,  64*31*31*192);
  pack_split_kernel<<<4096,256>>>(W3,   w3p,  64*31*31*192);
  pack_split_kernel<<<128, 256>>>(We1a, wa1p, 2*64*162);
  pack_split_kernel<<<1024,256>>>(We2a, wa2p, 29*64*243);

  spatial_kernel<<<dim3(32,16),256,SPAT_SM>>>(xp,  w1p, b1, s1p, nullptr, 1);
  spatial_kernel<<<dim3(32,16),256,SPAT_SM>>>(s1p, w2p, b2, s2p, nullptr, 31);
  spatial_kernel<<<dim3(32,16),256,SPAT_SM>>>(s2p, w3p, b3, s3p, s3f, 31);

  float* out = (float*)d_out;
  spec_ab_kernel<<<dim3(16,32,31),256,AB_SM>>>(s3p, wa1p,be1a,We1b,be1b,
                                               wa2p,be2a,We2b,be2b, hbuf);
  spec_c_kernel<<<dim3(8,32,31),256,C_SM>>>(hbuf, We1c,be1c,We2c,be2c, s3f, out);
}

// round 17
// speedup vs baseline: 2.1240x; 1.0560x over previous
#include <cuda_runtime.h>
#include <cstdint>
#include <cstddef>

typedef unsigned long long ull;

// Scratch (allocation-free rule: __device__ globals)
__device__ float    g_s3f[32*31*64*64];
__device__ uint32_t g_xp [32*64*64];
__device__ uint32_t g_s1p[32*31*64*64];
__device__ uint32_t g_s2p[32*31*64*64];
__device__ uint32_t g_s3p[32*31*64*64];
__device__ uint32_t g_W1p[64*31*192];
__device__ uint32_t g_W2p[64*31*31*192];
__device__ uint32_t g_W3p[64*31*31*192];
__device__ uint32_t g_wa1p[2*64*162];
__device__ uint32_t g_wa2p[29*64*243];
__device__ float    g_hb[31u*32*32*64*64];   // per-branch hb, 520MB

// ---- packed f32x2 helpers (conv-b / spec_c) ----
__device__ __forceinline__ void fma2(ull& d, ull a, ull b){
  asm("fma.rn.f32x2 %0, %1, %2, %0;" : "+l"(d) : "l"(a), "l"(b));
}
__device__ __forceinline__ ull dup2(float v){
  ull r; asm("mov.b64 %0, {%1, %1};" : "=l"(r) : "f"(v)); return r;
}
__device__ __forceinline__ ull pack2(float lo, float hi){
  ull r; asm("mov.b64 %0, {%1, %2};" : "=l"(r) : "f"(lo), "f"(hi)); return r;
}
__device__ __forceinline__ float2 ull2f(ull v){
  float2 f; asm("mov.b64 {%0, %1}, %2;" : "=f"(f.x), "=f"(f.y) : "l"(v)); return f;
}
__device__ __forceinline__ uint32_t smem_u32(const void* p){
  uint32_t a; asm("{ .reg .u64 t; cvta.to.shared.u64 t, %1; cvt.u32.u64 %0, t; }" : "=r"(a) : "l"(p)); return a;
}

// ---- mma.sync bf16 (base sm_80+ features: compiles for compute_103) ----
#define MMA_BF16(c0,c1,c2,c3,a0,a1,a2,a3,b0,b1) \
  asm("mma.sync.aligned.m16n8k16.row.col.f32.bf16.bf16.f32 " \
      "{%0,%1,%2,%3}, {%4,%5,%6,%7}, {%8,%9}, {%0,%1,%2,%3};" \
      : "+f"(c0),"+f"(c1),"+f"(c2),"+f"(c3) \
      : "r"(a0),"r"(a1),"r"(a2),"r"(a3),"r"(b0),"r"(b1))

#define LDSM_X4(r0,r1,r2,r3,addr) \
  asm volatile("ldmatrix.sync.aligned.m8n8.x4.shared.b16 {%0,%1,%2,%3}, [%4];" \
      : "=r"(r0),"=r"(r1),"=r"(r2),"=r"(r3) : "r"(addr))
#define LDSM_X2(r0,r1,addr) \
  asm volatile("ldmatrix.sync.aligned.m8n8.x2.shared.b16 {%0,%1}, [%2];" \
      : "=r"(r0),"=r"(r1) : "r"(addr))

// packed u32 = (bf16_hi << 16) | bf16_lo  (truncation split)
__device__ __forceinline__ uint32_t pack_split(float v){
  uint32_t u = __float_as_uint(v);
  uint32_t hi = u & 0xffff0000u;
  float r = v - __uint_as_float(hi);
  return hi | (__float_as_uint(r) >> 16);
}
__device__ __forceinline__ void unpack_pair(uint32_t pk0, uint32_t pk1,
                                            uint32_t& hp, uint32_t& lp){
  asm("prmt.b32 %0, %1, %2, 0x7632;" : "=r"(hp) : "r"(pk0), "r"(pk1));
  asm("prmt.b32 %0, %1, %2, 0x5410;" : "=r"(lp) : "r"(pk0), "r"(pk1));
}

// ---------------------------------------------------------------------------
// Pre-pass pack kernels (2 launches total, keeps ncu -s 5 on spec_ab)
// ---------------------------------------------------------------------------
extern "C" __global__ void pack4_kernel(
    const float* __restrict__ s0, uint32_t* __restrict__ d0, int n0,
    const float* __restrict__ s1, uint32_t* __restrict__ d1, int n1,
    const float* __restrict__ s2, uint32_t* __restrict__ d2, int n2,
    const float* __restrict__ s3_, uint32_t* __restrict__ d3, int n3)
{
  const float* s; uint32_t* d; int n;
  switch (blockIdx.y){
    case 0:  s=s0; d=d0; n=n0; break;
    case 1:  s=s1; d=d1; n=n1; break;
    case 2:  s=s2; d=d2; n=n2; break;
    default: s=s3_; d=d3; n=n3; break;
  }
  int i = blockIdx.x*blockDim.x + threadIdx.x;
  int stride = gridDim.x*blockDim.x;
  for (; i < n; i += stride) d[i] = pack_split(s[i]);
}
extern "C" __global__ void pack2_kernel(
    const float* __restrict__ s0, uint32_t* __restrict__ d0,
    const float* __restrict__ s1, uint32_t* __restrict__ d1, int n)
{
  const float* s = blockIdx.y ? s1 : s0;
  uint32_t*    d = blockIdx.y ? d1 : d0;
  int i = blockIdx.x*blockDim.x + threadIdx.x;
  int stride = gridDim.x*blockDim.x;
  for (; i < n; i += stride) d[i] = pack_split(s[i]);
}

// ---------------------------------------------------------------------------
// Spatial stage via mma.sync bf16 3-pass hi/lo, packed-split I/O.
// GEMM per block: M=128 px (2 b x 64 w), N=64 (2 f x 32 o, o=31 zero),
// K=Cin*192 as 3 chunks of 64 per i. Grid (fpair=32, bpair=16), block 256.
// smem: in_pk u32 2x64x66 @0 (33792) | sbias @33792 (256) | off_tab @34048 (768)
//   Ahi @34816 (128x144B) | Alo @53248 | Bhi @71680 (64x144B) | Blo @80896 (end 90112)
// ---------------------------------------------------------------------------
extern "C" __global__ void __launch_bounds__(256,2) spatial_kernel(
    const uint32_t* __restrict__ inp, const uint32_t* __restrict__ Wp,
    const float* __restrict__ bias, uint32_t* __restrict__ outp,
    float* __restrict__ outf, int Cin)
{
  extern __shared__ char smem_raw[];
  uint32_t* in_pk = (uint32_t*)smem_raw;
  float* sbias    = (float*)(smem_raw + 33792);
  int*   off_tab  = (int*)  (smem_raw + 34048);
  uint32_t* Ahi_w = (uint32_t*)(smem_raw + 34816);
  uint32_t* Alo_w = (uint32_t*)(smem_raw + 53248);
  uint32_t* Bhi_w = (uint32_t*)(smem_raw + 71680);
  uint32_t* Blo_w = (uint32_t*)(smem_raw + 80896);
  const uint32_t sbase = smem_u32(smem_raw);
  const uint32_t AHI = sbase + 34816, ALO = sbase + 53248;
  const uint32_t BHI = sbase + 71680, BLO = sbase + 80896;

  const int f0 = blockIdx.x*2;
  const int b0 = blockIdx.y*2;
  const int t = threadIdx.x;
  const int w = t>>5, lane = t&31;
  const int mw = w&3, nw = w>>2;

  if (t < 128){ in_pk[t*66] = 0u; in_pk[t*66+65] = 0u; }
  if (t < 64){
    int ff = t>>5, o = t&31;
    sbias[t] = (o<31) ? bias[(f0+ff)*31+o] : 0.f;
  }
  if (t < 192) off_tab[t] = (t/3)*66 + (t%3);

  const int arow0 = w*16 + (lane>>2);
  const int kpb   = lane&3;
  const int chb   = w*8 + (lane>>2);
  const int bff = chb>>5, bo = chb&31;
  const uint32_t* wrow_base = nullptr;
  if (bo < 31)
    wrow_base = Wp + ((size_t)((f0+bff)*31 + bo))*Cin*192;

  float acc[2][4][4];
  #pragma unroll
  for (int mt=0;mt<2;mt++)
    #pragma unroll
    for (int nt=0;nt<4;nt++)
      #pragma unroll
      for (int q=0;q<4;q++) acc[mt][nt][q] = 0.f;

  #pragma unroll 1
  for (int i=0;i<Cin;i++){
    // vectorized staging of both input images (LDG.128)
    #pragma unroll 1
    for (int bb=0;bb<2;bb++){
      const uint4* gin = (const uint4*)(inp + ((size_t)((b0+bb)*Cin + i) << 12));
      for (int idx = t; idx < 1024; idx += 256){
        uint4 v = gin[idx];
        uint32_t* dst = &in_pk[bb*4224 + (idx>>4)*66 + 1 + ((idx&15)<<2)];
        dst[0]=v.x; dst[1]=v.y; dst[2]=v.z; dst[3]=v.w;
      }
    }
    const uint32_t* wrow = wrow_base ? (wrow_base + (size_t)i*192) : nullptr;
    __syncthreads();

    #pragma unroll 1
    for (int c=0;c<3;c++){
      // ---- stage A: j outer (off_tab hoisted), 2 rows inner ----
      const uint32_t* inb0 = in_pk + ((arow0  )>>6)*4224 + ((arow0  )&63);
      const uint32_t* inb1 = in_pk + ((arow0+8)>>6)*4224 + ((arow0+8)&63);
      #pragma unroll
      for (int j=0;j<8;j++){
        int kp = kpb + 4*j;
        int kloc = c*64 + 2*kp;
        int o0 = off_tab[kloc], o1 = off_tab[kloc+1];
        {
          uint32_t hp, lp; unpack_pair(inb0[o0], inb0[o1], hp, lp);
          Ahi_w[arow0*36+kp] = hp;  Alo_w[arow0*36+kp] = lp;
        }
        {
          uint32_t hp, lp; unpack_pair(inb1[o0], inb1[o1], hp, lp);
          Ahi_w[(arow0+8)*36+kp] = hp;  Alo_w[(arow0+8)*36+kp] = lp;
        }
      }
      // ---- stage B: 1 row x 8 k-pairs (LDG.64) ----
      #pragma unroll
      for (int j=0;j<8;j++){
        int kp = kpb + 4*j;
        int kloc = c*64 + 2*kp;
        uint32_t pk0 = 0u, pk1 = 0u;
        if (wrow){
          ull v2 = *(const ull*)(wrow + kloc);
          pk0 = (uint32_t)v2; pk1 = (uint32_t)(v2>>32);
        }
        uint32_t hp, lp; unpack_pair(pk0, pk1, hp, lp);
        Bhi_w[chb*36+kp] = hp;
        Blo_w[chb*36+kp] = lp;
      }
      __syncthreads();

      // ---- MMA over 4 k16 tiles ----
      #pragma unroll 1
      for (int kt=0;kt<4;kt++){
        uint32_t ah[2][4], al[2][4];
        #pragma unroll
        for (int mt=0;mt<2;mt++){
          uint32_t arow = (uint32_t)(mw*32 + mt*16 + (lane&15));
          uint32_t aoff = arow*144u + (uint32_t)(kt*32) + (((uint32_t)lane>>4)<<4);
          LDSM_X4(ah[mt][0],ah[mt][1],ah[mt][2],ah[mt][3], AHI + aoff);
          LDSM_X4(al[mt][0],al[mt][1],al[mt][2],al[mt][3], ALO + aoff);
        }
        #pragma unroll
        for (int ntp=0;ntp<2;ntp++){
          uint32_t brow = (uint32_t)(nw*32 + ntp*16 + (((lane>>4)&1u)<<3) + (lane&7));
          uint32_t boff = brow*144u + (uint32_t)(kt*32) + ((((uint32_t)lane>>3)&1u)<<4);
          uint32_t bh[4], bl[4];
          LDSM_X4(bh[0],bh[1],bh[2],bh[3], BHI + boff);
          LDSM_X4(bl[0],bl[1],bl[2],bl[3], BLO + boff);
          #pragma unroll
          for (int h=0;h<2;h++){
            int nt = ntp*2 + h;
            #pragma unroll
            for (int mt=0;mt<2;mt++){
              MMA_BF16(acc[mt][nt][0],acc[mt][nt][1],acc[mt][nt][2],acc[mt][nt][3],
                       ah[mt][0],ah[mt][1],ah[mt][2],ah[mt][3], bh[2*h],bh[2*h+1]);
              MMA_BF16(acc[mt][nt][0],acc[mt][nt][1],acc[mt][nt][2],acc[mt][nt][3],
                       ah[mt][0],ah[mt][1],ah[mt][2],ah[mt][3], bl[2*h],bl[2*h+1]);
              MMA_BF16(acc[mt][nt][0],acc[mt][nt][1],acc[mt][nt][2],acc[mt][nt][3],
                       al[mt][0],al[mt][1],al[mt][2],al[mt][3], bh[2*h],bh[2*h+1]);
            }
          }
        }
      }
      __syncthreads();
    }
  }

  // ---- epilogue: bias + relu -> packed out (+ optional fp32) ----
  #pragma unroll
  for (int mt=0;mt<2;mt++){
    #pragma unroll
    for (int nt=0;nt<4;nt++){
      #pragma unroll
      for (int q=0;q<4;q++){
        int r  = mw*32 + mt*16 + (lane>>2) + ((q>>1)<<3);
        int cn = nw*32 + nt*8 + (lane&3)*2 + (q&1);
        int o = cn & 31;
        if (o < 31){
          int bb = r>>6, ww = r&63;
          int ff = cn>>5;
          float v = fmaxf(acc[mt][nt][q] + sbias[cn], 0.f);
          size_t idx = (((size_t)((b0+bb)*31 + o))*64 + (f0+ff))*64 + ww;
          outp[idx] = pack_split(v);
          if (outf) outf[idx] = v;
        }
      }
    }
  }
}

// ---------------------------------------------------------------------------
// Spectral conv-a via mma.sync bf16 3-pass hi/lo (packed-split inputs)
// + conv-b FFMA2. Grid (16,32,31), block 256. Layout as R16 winner.
// ---------------------------------------------------------------------------
extern "C" __global__ void __launch_bounds__(256,2) spec_ab_kernel(
    const uint32_t* __restrict__ s3p,
    const uint32_t* __restrict__ wa1p, const float* __restrict__ be1a,
    const float* __restrict__ We1b, const float* __restrict__ be1b,
    const uint32_t* __restrict__ wa2p, const float* __restrict__ be2a,
    const float* __restrict__ We2b, const float* __restrict__ be2b,
    float* __restrict__ hb_all)
{
  extern __shared__ char smem_raw[];
  uint32_t* in_pk = (uint32_t*)(smem_raw);
  float* sbias   = (float*)(smem_raw + 6912);
  int*   off_tab = (int*)  (smem_raw + 7168);
  float* wbT     = (float*)(smem_raw + 8192);
  uint32_t* Ahi_w = (uint32_t*)(smem_raw + 17408);
  uint32_t* Alo_w = (uint32_t*)(smem_raw + 54272);
  uint32_t* Bhi_w = (uint32_t*)(smem_raw + 91136);
  uint32_t* Blo_w = (uint32_t*)(smem_raw + 100352);
  float* haS = (float*)(smem_raw + 17408);
  const uint32_t sbase = smem_u32(smem_raw);
  const uint32_t AHI = sbase + 17408, ALO = sbase + 54272;
  const uint32_t BHI = sbase + 91136, BLO = sbase + 100352;

  const int br = blockIdx.z;
  const uint32_t* wap; const float *ba, *wb, *bb; int c0, Cin;
  if (br == 0){
    Cin=2; c0=0;  wap=wa1p;        ba=be1a;    wb=We1b;      bb=be1b;
  } else if (br == 30){
    Cin=2; c0=29; wap=wa1p+10368;  ba=be1a+64; wb=We1b+2048; bb=be1b+32;
  } else {
    int m = br-1; Cin=3; c0=m;
    wap=wa2p+(size_t)m*15552; ba=be2a+(size_t)m*64;
    wb=We2b+(size_t)m*2048;   bb=be2b+(size_t)m*32;
  }
  const int Ck = Cin*81;
  const int nchunk = (Ck + 63) >> 6;

  const int b = blockIdx.y;
  const int tile = blockIdx.x;
  const int ty0 = (tile>>2)*16, tx0 = (tile&3)*16;
  const int t = threadIdx.x;
  const int w = t>>5, lane = t&31;

  for (int idx = t; idx < Cin*576; idx += 256){
    int ci = idx/576, r = idx - ci*576;
    int yy = r/24, xx = r - yy*24;
    int gy = ty0-4+yy, gx = tx0-4+xx;
    uint32_t v = 0u;
    if ((unsigned)gy < 64u && (unsigned)gx < 64u)
      v = s3p[(((size_t)(b*31 + c0 + ci))*64 + gy)*64 + gx];
    in_pk[idx] = v;
  }
  if (t < 64) sbias[t] = ba[t];
  {
    int k = t;
    int off = -1;
    if (k < Ck){
      int ci = k/81, r = k - ci*81;
      off = ci*576 + (r/9)*24 + (r%9);
    }
    off_tab[k] = off;
  }
  for (int idx = t; idx < 2048; idx += 256){
    int c = idx & 31, k = idx >> 5;
    wbT[k*36 + c] = wb[c*64 + k];
  }

  float acc[2][8][4];
  #pragma unroll
  for (int mt=0;mt<2;mt++)
    #pragma unroll
    for (int nt=0;nt<8;nt++)
      #pragma unroll
      for (int q=0;q<4;q++) acc[mt][nt][q] = 0.f;

  const int pxb = w*32 + (lane>>2);
  const int kpb = lane&3;
  const int chb = w*8 + (lane>>2);

  // px offsets for the 4 A-rows this thread stages (loop-invariant)
  int poffv[4];
  #pragma unroll
  for (int i=0;i<4;i++){
    int px = pxb + 8*i;
    poffv[i] = (px>>4)*24 + (px&15);
  }

  #pragma unroll 1
  for (int c = 0; c < nchunk; c++){
    __syncthreads();
    // ---- stage A: j outer (off_tab hoisted), 4 px rows inner ----
    #pragma unroll
    for (int j=0;j<8;j++){
      int kp = kpb + 4*j;
      int k0 = c*64 + 2*kp;
      int o0 = off_tab[k0];
      int o1 = off_tab[k0+1];
      #pragma unroll
      for (int i=0;i<4;i++){
        int px = pxb + 8*i;
        uint32_t pk0 = (o0>=0)? in_pk[o0+poffv[i]] : 0u;
        uint32_t pk1 = (o1>=0)? in_pk[o1+poffv[i]] : 0u;
        uint32_t hp, lp; unpack_pair(pk0, pk1, hp, lp);
        Ahi_w[px*36+kp] = hp;
        Alo_w[px*36+kp] = lp;
      }
    }
    #pragma unroll
    for (int j=0;j<8;j++){
      int kp = kpb + 4*j;
      int k0 = c*64 + 2*kp;
      uint32_t pk0 = (k0   < Ck)? wap[chb*Ck+k0]   : 0u;
      uint32_t pk1 = (k0+1 < Ck)? wap[chb*Ck+k0+1] : 0u;
      uint32_t hp, lp; unpack_pair(pk0, pk1, hp, lp);
      Bhi_w[chb*36+kp] = hp;
      Blo_w[chb*36+kp] = lp;
    }
    __syncthreads();

    #pragma unroll 1
    for (int kt=0;kt<4;kt++){
      uint32_t ah[2][4], al[2][4];
      #pragma unroll
      for (int mt=0;mt<2;mt++){
        uint32_t arow = (uint32_t)(w*32 + mt*16 + (lane&15));
        uint32_t aoff = arow*144u + (uint32_t)(kt*32) + (((uint32_t)lane>>4)<<4);
        LDSM_X4(ah[mt][0],ah[mt][1],ah[mt][2],ah[mt][3], AHI + aoff);
        LDSM_X4(al[mt][0],al[mt][1],al[mt][2],al[mt][3], ALO + aoff);
      }
      #pragma unroll
      for (int ntp=0;ntp<4;ntp++){
        uint32_t brow = (uint32_t)(ntp*16 + (((lane>>4)&1u)<<3) + (lane&7));
        uint32_t boff = brow*144u + (uint32_t)(kt*32) + ((((uint32_t)lane>>3)&1u)<<4);
        uint32_t bh[4], bl[4];
        LDSM_X4(bh[0],bh[1],bh[2],bh[3], BHI + boff);
        LDSM_X4(bl[0],bl[1],bl[2],bl[3], BLO + boff);
        #pragma unroll
        for (int h=0;h<2;h++){
          int nt = ntp*2 + h;
          #pragma unroll
          for (int mt=0;mt<2;mt++){
            MMA_BF16(acc[mt][nt][0],acc[mt][nt][1],acc[mt][nt][2],acc[mt][nt][3],
                     ah[mt][0],ah[mt][1],ah[mt][2],ah[mt][3], bh[2*h],bh[2*h+1]);
            MMA_BF16(acc[mt][nt][0],acc[mt][nt][1],acc[mt][nt][2],acc[mt][nt][3],
                     ah[mt][0],ah[mt][1],ah[mt][2],ah[mt][3], bl[2*h],bl[2*h+1]);
            MMA_BF16(acc[mt][nt][0],acc[mt][nt][1],acc[mt][nt][2],acc[mt][nt][3],
                     al[mt][0],al[mt][1],al[mt][2],al[mt][3], bh[2*h],bh[2*h+1]);
          }
        }
      }
    }
  }
  __syncthreads();

  // ---- epilogue: bias+relu -> haS channel-major (pitch 260) ----
  #pragma unroll
  for (int mt=0;mt<2;mt++){
    int r0 = w*32 + mt*16 + (lane>>2);
    #pragma unroll
    for (int nt=0;nt<8;nt++){
      int cc = nt*8 + (lane&3)*2;
      float b0v = sbias[cc], b1v = sbias[cc+1];
      haS[cc*260 + r0]        = fmaxf(acc[mt][nt][0]+b0v, 0.f);
      haS[(cc+1)*260 + r0]    = fmaxf(acc[mt][nt][1]+b1v, 0.f);
      haS[cc*260 + r0+8]      = fmaxf(acc[mt][nt][2]+b0v, 0.f);
      haS[(cc+1)*260 + r0+8]  = fmaxf(acc[mt][nt][3]+b1v, 0.f);
    }
  }
  __syncthreads();

  // ---- conv-b: thread = (pq<64: 4 px, c4<4: 8 out-ch as 4 pairs) ----
  const int pq = t >> 2, c4 = t & 3;
  ull a2[4][4];
  #pragma unroll
  for (int j=0;j<4;j++){
    ull bp = pack2(bb[c4*8 + 2*j], bb[c4*8 + 2*j + 1]);
    #pragma unroll
    for (int p=0;p<4;p++) a2[j][p] = bp;
  }
  #pragma unroll 4
  for (int k=0;k<64;k++){
    float4 pv = *(const float4*)(haS + k*260 + pq*4);
    ull d0 = dup2(pv.x), d1 = dup2(pv.y), d2 = dup2(pv.z), d3 = dup2(pv.w);
    const float* wr = wbT + k*36 + c4*8;
    ulonglong2 wv0 = *(const ulonglong2*)(wr);
    ulonglong2 wv1 = *(const ulonglong2*)(wr + 4);
    fma2(a2[0][0], wv0.x, d0); fma2(a2[0][1], wv0.x, d1);
    fma2(a2[0][2], wv0.x, d2); fma2(a2[0][3], wv0.x, d3);
    fma2(a2[1][0], wv0.y, d0); fma2(a2[1][1], wv0.y, d1);
    fma2(a2[1][2], wv0.y, d2); fma2(a2[1][3], wv0.y, d3);
    fma2(a2[2][0], wv1.x, d0); fma2(a2[2][1], wv1.x, d1);
    fma2(a2[2][2], wv1.x, d2); fma2(a2[2][3], wv1.x, d3);
    fma2(a2[3][0], wv1.y, d0); fma2(a2[3][1], wv1.y, d1);
    fma2(a2[3][2], wv1.y, d2); fma2(a2[3][3], wv1.y, d3);
  }

  float* hb = hb_all + (size_t)br * (32u*32*64*64);
  const int gy = ty0 + (pq>>2), gx0 = tx0 + (pq&3)*4;
  #pragma unroll
  for (int j=0;j<4;j++){
    float2 p0 = ull2f(a2[j][0]);
    float2 p1 = ull2f(a2[j][1]);
    float2 p2 = ull2f(a2[j][2]);
    float2 p3 = ull2f(a2[j][3]);
    int ch0 = c4*8 + 2*j;
    float4 o0, o1;
    o0.x=fmaxf(p0.x,0.f); o0.y=fmaxf(p1.x,0.f); o0.z=fmaxf(p2.x,0.f); o0.w=fmaxf(p3.x,0.f);
    o1.x=fmaxf(p0.y,0.f); o1.y=fmaxf(p1.y,0.f); o1.z=fmaxf(p2.y,0.f); o1.w=fmaxf(p3.y,0.f);
    *(float4*)&hb[(((size_t)(b*32 + ch0  ))*64 + gy)*64 + gx0] = o0;
    *(float4*)&hb[(((size_t)(b*32 + ch0+1))*64 + gy)*64 + gx0] = o1;
  }
}

// ---------------------------------------------------------------------------
// Spectral conv-c (unchanged) + residual add + NHWC transpose store.
// ---------------------------------------------------------------------------
extern "C" __global__ void __launch_bounds__(256,2) spec_c_kernel(
    const float* __restrict__ hb_all,
    const float* __restrict__ We1c, const float* __restrict__ be1c,
    const float* __restrict__ We2c, const float* __restrict__ be2c,
    const float* __restrict__ s3, float* __restrict__ outp)
{
  extern __shared__ float sm[];
  float* in_sh = sm;
  float* wd    = sm + 23040;

  const int br = blockIdx.z;
  const float *wc, *bc;
  if (br == 0)      { wc=We1c;                 bc=be1c;   }
  else if (br == 30){ wc=We1c+800;             bc=be1c+1; }
  else              { wc=We2c+(size_t)(br-1)*800; bc=be2c+(br-1); }
  const int cbr = br;
  const float* hb = hb_all + (size_t)br * (32u*32*64*64);

  const int b = blockIdx.y;
  const int tile = blockIdx.x;
  const int ty0 = (tile>>1)*16, tx0 = (tile&1)*32;
  const int t = threadIdx.x;

  for (int idx=t; idx<800; idx+=256){
    float w = wc[idx];
    wd[2*idx] = w; wd[2*idx+1] = w;
  }
  for (int idx=t; idx<23040; idx+=256){
    int c = idx/720, r = idx - c*720;
    int yy = r/36, xx = r - yy*36;
    int gy = ty0-2+yy, gx = tx0-2+xx;
    float v=0.f;
    if ((unsigned)gy<64u && (unsigned)gx<64u)
      v = hb[(((size_t)(b*32+c))*64+gy)*64+gx];
    in_sh[idx]=v;
  }
  __syncthreads();

  const int px0 = t*2;
  const int y = px0>>5, x = px0&31;
  ull acc = dup2(bc[0]);
  #pragma unroll 1
  for (int c=0;c<32;c++){
    #pragma unroll
    for (int dy=0;dy<5;dy++){
      const float* row = in_sh + (c*20 + y + dy)*36 + x;
      ull q0 = *(const ull*)(row);
      ull q2 = *(const ull*)(row+2);
      ull q4 = *(const ull*)(row+4);
      float2 f0 = ull2f(q0), f2v = ull2f(q2), f4 = ull2f(q4);
      ull q1 = pack2(f0.y, f2v.x);
      ull q3 = pack2(f2v.y, f4.x);
      const ull* wr = (const ull*)(wd + (c*25 + dy*5)*2);
      fma2(acc, wr[0], q0);
      fma2(acc, wr[1], q1);
      fma2(acc, wr[2], q2);
      fma2(acc, wr[3], q3);
      fma2(acc, wr[4], q4);
    }
  }
  float2 a = ull2f(acc);
  const int gy = ty0+y, gx = tx0+x;
  const float* s3p = s3 + (((size_t)(b*31+cbr))*64 + gy)*64 + gx;
  float* op = outp + (((size_t)(b*64+gy))*64 + gx)*31 + cbr;
  op[0]  = s3p[0] + a.x;
  op[31] = s3p[1] + a.y;
}

// ---------------------------------------------------------------------------
extern "C" void kernel_launch(void* const* d_in, const int* in_sizes, int n_in,
                              void* d_out, int out_size)
{
  (void)in_sizes; (void)n_in; (void)out_size;
  const float* x    = (const float*)d_in[0];
  const float* W1   = (const float*)d_in[1];
  const float* b1   = (const float*)d_in[2];
  const float* W2   = (const float*)d_in[3];
  const float* b2   = (const float*)d_in[4];
  const float* W3   = (const float*)d_in[5];
  const float* b3   = (const float*)d_in[6];
  const float* We1a = (const float*)d_in[7];
  const float* be1a = (const float*)d_in[8];
  const float* We1b = (const float*)d_in[9];
  const float* be1b = (const float*)d_in[10];
  const float* We1c = (const float*)d_in[11];
  const float* be1c = (const float*)d_in[12];
  const float* We2a = (const float*)d_in[13];
  const float* be2a = (const float*)d_in[14];
  const float* We2b = (const float*)d_in[15];
  const float* be2b = (const float*)d_in[16];
  const float* We2c = (const float*)d_in[17];
  const float* be2c = (const float*)d_in[18];

  float *s3f, *hbuf;
  uint32_t *xp,*s1p,*s2p,*s3p,*w1p,*w2p,*w3p,*wa1p,*wa2p;
  cudaGetSymbolAddress((void**)&s3f,  g_s3f);
  cudaGetSymbolAddress((void**)&hbuf, g_hb);
  cudaGetSymbolAddress((void**)&xp,   g_xp);
  cudaGetSymbolAddress((void**)&s1p,  g_s1p);
  cudaGetSymbolAddress((void**)&s2p,  g_s2p);
  cudaGetSymbolAddress((void**)&s3p,  g_s3p);
  cudaGetSymbolAddress((void**)&w1p,  g_W1p);
  cudaGetSymbolAddress((void**)&w2p,  g_W2p);
  cudaGetSymbolAddress((void**)&w3p,  g_W3p);
  cudaGetSymbolAddress((void**)&wa1p, g_wa1p);
  cudaGetSymbolAddress((void**)&wa2p, g_wa2p);

  const int SPAT_SM = 90112;
  const int AB_SM   = 109568;
  const int C_SM    = (23040 + 1600)*4;
  cudaFuncSetAttribute(spatial_kernel, cudaFuncAttributeMaxDynamicSharedMemorySize, SPAT_SM);
  cudaFuncSetAttribute(spec_ab_kernel, cudaFuncAttributeMaxDynamicSharedMemorySize, AB_SM);
  cudaFuncSetAttribute(spec_c_kernel,  cudaFuncAttributeMaxDynamicSharedMemorySize, C_SM);

  // ---- pre-pass (2 launches; keeps ncu -s 5 capture on spec_ab) ----
  pack4_kernel<<<dim3(1792,4),256>>>(x,    xp,   32*64*64,
                                     W1,   w1p,  64*31*192,
                                     We1a, wa1p, 2*64*162,
                                     We2a, wa2p, 29*64*243);
  pack2_kernel<<<dim3(4096,2),256>>>(W2, w2p, W3, w3p, 64*31*31*192);

  spatial_kernel<<<dim3(32,16),256,SPAT_SM>>>(xp,  w1p, b1, s1p, nullptr, 1);
  spatial_kernel<<<dim3(32,16),256,SPAT_SM>>>(s1p, w2p, b2, s2p, nullptr, 31);
  spatial_kernel<<<dim3(32,16),256,SPAT_SM>>>(s2p, w3p, b3, s3p, s3f, 31);

  float* out = (float*)d_out;
  spec_ab_kernel<<<dim3(16,32,31),256,AB_SM>>>(s3p, wa1p,be1a,We1b,be1b,
                                               wa2p,be2a,We2b,be2b, hbuf);
  spec_c_kernel<<<dim3(8,32,31),256,C_SM>>>(hbuf, We1c,be1c,We2c,be2c, s3f, out);
}